// round 14
// baseline (speedup 1.0000x reference)
#include <cuda_runtime.h>
#include <cuda_fp16.h>
#include <math.h>
#include <stdint.h>

// ---------------- problem constants ----------------
#define SEQ      4096
#define HIDDEN   1152
#define HEADS    16
#define HD       72
#define INTER    4304
#define DEPTH    6
#define MERGED   4608
#define OUTH     2048
#define PATCHD   1536
#define IMG_TOK  1024
#define NBH      64
#define SCALE_Q  0.11785113019775793f

// ---------------- device scratch ----------------
__device__ __half w16_patch[HIDDEN*PATCHD];
__device__ __half w16_qkv [DEPTH*3*HIDDEN*HIDDEN];
__device__ __half w16_proj[DEPTH*HIDDEN*HIDDEN];
__device__ __half w16_fc1 [DEPTH*INTER*HIDDEN];
__device__ __half w16_fc2 [DEPTH*HIDDEN*INTER];
__device__ __half w16_mfc1[MERGED*MERGED];
__device__ __half w16_mfc2[OUTH*MERGED];
__device__ __half w16_dfc1[2*MERGED*MERGED];
__device__ __half w16_dfc2[2*OUTH*MERGED];
__device__ __half g_px16  [SEQ*PATCHD];
__device__ __half g_xn16  [SEQ*HIDDEN];
__device__ __half g_qkv16 [SEQ*3*HIDDEN];
__device__ __half g_q16   [NBH*IMG_TOK*HD];
__device__ __half g_k16   [NBH*IMG_TOK*HD];
__device__ __half g_v16t  [NBH*HD*IMG_TOK];
__device__ __half g_at16  [SEQ*HIDDEN];
__device__ __half g_h16   [SEQ*INTER];
__device__ __half g_mh16  [SEQ*HIDDEN];
__device__ __half g_mf16  [1024*MERGED];
__device__ float g_x   [SEQ*HIDDEN];
__device__ float g_cos [IMG_TOK*HD];
__device__ float g_sin [IMG_TOK*HD];

// ---------------- helpers ----------------
__device__ __forceinline__ float gelu_f(float x){
    float x3 = x*x*x;
    return 0.5f*x*(1.0f + tanhf(0.7978845608028654f*(x + 0.044715f*x3)));
}
__device__ __forceinline__ uint32_t h2u(float a, float b){
    __half2 h = __floats2half2_rn(a, b);
    return *(uint32_t*)&h;
}
__device__ __forceinline__ void mma16(float* c, const uint32_t* a, const uint32_t* b){
    asm volatile("mma.sync.aligned.m16n8k16.row.col.f32.f16.f16.f32 "
        "{%0,%1,%2,%3},{%4,%5,%6,%7},{%8,%9},{%0,%1,%2,%3};"
        : "+f"(c[0]),"+f"(c[1]),"+f"(c[2]),"+f"(c[3])
        : "r"(a[0]),"r"(a[1]),"r"(a[2]),"r"(a[3]),"r"(b[0]),"r"(b[1]));
}
#define LDSM4(r, addr) \
    asm volatile("ldmatrix.sync.aligned.m8n8.x4.shared.b16 {%0,%1,%2,%3}, [%4];" \
        : "=r"((r)[0]),"=r"((r)[1]),"=r"((r)[2]),"=r"((r)[3]) : "r"(addr))
__device__ __forceinline__ void cp16(void* dst, const void* src, int nbytes){
    asm volatile("cp.async.cg.shared.global [%0], [%1], 16, %2;"
        :: "r"((uint32_t)__cvta_generic_to_shared(dst)), "l"(src), "r"(nbytes) : "memory");
}
#define CP_COMMIT() asm volatile("cp.async.commit_group;" ::: "memory")
#define CP_WAIT1()  asm volatile("cp.async.wait_group 1;" ::: "memory")
#define CP_WAIT0()  asm volatile("cp.async.wait_group 0;" ::: "memory")

__device__ __forceinline__ float blockReduceSum(float v, float* sh){
    int tid = threadIdx.x;
    __syncthreads();
    #pragma unroll
    for(int o=16;o>0;o>>=1) v += __shfl_xor_sync(0xffffffffu, v, o);
    if((tid&31)==0) sh[tid>>5] = v;
    __syncthreads();
    if(tid < 32){
        float r = (tid < (int)(blockDim.x>>5)) ? sh[tid] : 0.f;
        #pragma unroll
        for(int o=16;o>0;o>>=1) r += __shfl_xor_sync(0xffffffffu, r, o);
        if(tid==0) sh[0] = r;
    }
    __syncthreads();
    return sh[0];
}

// ---------------- vectorized fp32 -> fp16 ----------------
__global__ void f2h(const float4* __restrict__ s, __half2* __restrict__ d, long n4){
    long i = (long)blockIdx.x*blockDim.x + threadIdx.x;
    long stride = (long)gridDim.x*blockDim.x;
    for(; i<n4; i+=stride){
        float4 v = s[i];
        d[2*i  ] = __floats2half2_rn(v.x, v.y);
        d[2*i+1] = __floats2half2_rn(v.z, v.w);
    }
}

// ---------------- fp16 GEMM: 256x128, 512 thr, K-chunk 64, 3-stage, 1 barrier/iter ----------------
#define GST 72
#define A_STG (256*GST)        // A stage: 18432 halfs
#define B_STG (128*GST)        // B stage: 9216 halfs
#define GSMEM ((3*A_STG + 3*B_STG)*2)   // 165888 bytes

__global__ __launch_bounds__(512,1)
void gemm_a(const __half* __restrict__ A, const __half* __restrict__ B,
            void* __restrict__ Cv, const float* __restrict__ bias,
            const float* __restrict__ res,
            int M, int N, int K, int flags)   // flags: 1=gelu, 2=out fp16
{
    extern __shared__ __half smh[];
    __half* As = smh;
    __half* Bs = smh + 3*A_STG;

    const int tid  = threadIdx.x;
    const int lane = tid & 31, warp = tid >> 5;
    const int g = lane >> 2, tq = lane & 3;
    const int wm = warp >> 1, wn = warp & 1;   // 8 (m) x 2 (n)
    const int m0 = wm*32, n0 = wn*64;
    const int bn = blockIdx.x, bm = blockIdx.y;

    float acc[2][8][4];
    #pragma unroll
    for(int i=0;i<2;i++)
        #pragma unroll
        for(int j=0;j<8;j++)
            #pragma unroll
            for(int q=0;q<4;q++) acc[i][j][q]=0.f;

    const int NT = (K+63)/64;
    const int lr  = tid >> 3;     // 0..63
    const int seg = tid & 7;      // 16B segment within 128B k-row

    auto loadStage = [&](int st, int k0){
        int kh  = k0 + seg*8;
        int nb  = (K - kh)*2; nb = nb < 0 ? 0 : (nb > 16 ? 16 : nb);
        int khc = kh < K ? kh : 0;
        #pragma unroll
        for(int i=0;i<4;i++){
            int row = lr + i*64;
            cp16(As + st*A_STG + row*GST + seg*8,
                 A + (long)(bm*256+row)*K + khc, nb);
        }
        #pragma unroll
        for(int i=0;i<2;i++){
            int row = lr + i*64;
            int brow = bn*128 + row;
            cp16(Bs + st*B_STG + row*GST + seg*8,
                 B + (long)(brow < N ? brow : 0)*K + khc, brow < N ? nb : 0);
        }
    };

    loadStage(0, 0); CP_COMMIT();
    if(NT > 1){ loadStage(1, 64); CP_COMMIT(); }

    for(int kt=0; kt<NT; kt++){
        if(kt+1 < NT){ CP_WAIT1(); } else { CP_WAIT0(); }
        __syncthreads();

        const int st = kt % 3;
        const uint32_t abase = (uint32_t)__cvta_generic_to_shared(As + st*A_STG);
        const uint32_t bbase = (uint32_t)__cvta_generic_to_shared(Bs + st*B_STG);
        const int lrow = lane & 15, lcol = (lane >> 4) * 8;
        #pragma unroll
        for(int s=0;s<4;s++){
            uint32_t af[2][4];
            #pragma unroll
            for(int mt=0;mt<2;mt++){
                uint32_t ad = abase + ((m0 + mt*16 + lrow)*GST + s*16 + lcol)*2;
                LDSM4(af[mt], ad);
            }
            uint32_t bq[4][4];
            #pragma unroll
            for(int p=0;p<4;p++){
                uint32_t bd = bbase + ((n0 + p*16 + lrow)*GST + s*16 + lcol)*2;
                LDSM4(bq[p], bd);
            }
            #pragma unroll
            for(int mt=0;mt<2;mt++)
                #pragma unroll
                for(int nt=0;nt<8;nt++){
                    uint32_t bf[2] = { bq[nt>>1][nt&1], bq[nt>>1][2+(nt&1)] };
                    mma16(acc[mt][nt], af[mt], bf);
                }
        }
        if(kt+2 < NT){ loadStage((kt+2)%3, (kt+2)*64); CP_COMMIT(); }
    }

    const int dogelu = flags & 1, out16 = flags & 2;
    float* Cf = (float*)Cv;
    __half* Ch = (__half*)Cv;
    #pragma unroll
    for(int mt=0;mt<2;mt++){
        int r0 = bm*256 + m0 + mt*16 + g;
        int r1 = r0 + 8;
        #pragma unroll
        for(int nt=0;nt<8;nt++){
            int col = bn*128 + n0 + nt*8 + tq*2;
            if(col < N){
                float v0 = acc[mt][nt][0], v1 = acc[mt][nt][1];
                float v2 = acc[mt][nt][2], v3 = acc[mt][nt][3];
                if(bias){ float b0=bias[col], b1=bias[col+1]; v0+=b0; v1+=b1; v2+=b0; v3+=b1; }
                if(dogelu){ v0=gelu_f(v0); v1=gelu_f(v1); v2=gelu_f(v2); v3=gelu_f(v3); }
                long i0 = (long)r0*N + col, i1 = (long)r1*N + col;
                if(out16){
                    *(__half2*)(Ch + i0) = __floats2half2_rn(v0, v1);
                    *(__half2*)(Ch + i1) = __floats2half2_rn(v2, v3);
                } else {
                    if(res){ v0+=res[i0]; v1+=res[i0+1]; v2+=res[i1]; v3+=res[i1+1]; }
                    Cf[i0]=v0; Cf[i0+1]=v1; Cf[i1]=v2; Cf[i1+1]=v3;
                }
            }
        }
    }
}

// ---------------- fused flash attention: 3-stage cp.async K/V pipeline ----------------
#define QST 44
#define VST 36
#define K_ST (64*QST)
#define V_ST (72*VST)
#define FSMEM ((128*QST + 3*K_ST + 3*V_ST)*4)   // 87424 bytes

__global__ __launch_bounds__(256,2)
void flash_attn(const __half* __restrict__ q2, const __half* __restrict__ k2,
                const __half* __restrict__ v2t, __half* __restrict__ attn)
{
    extern __shared__ uint32_t fsm[];
    uint32_t* Qs = fsm;
    uint32_t* Ks = fsm + 128*QST;
    uint32_t* Vs = Ks + 3*K_ST;

    const int tid = threadIdx.x;
    const int lane = tid & 31, w = tid >> 5;
    const int g = lane >> 2, tq = lane & 3;
    const int qb = blockIdx.x, bh = blockIdx.y;

    const __half* Kg0 = k2  + (long)bh*IMG_TOK*HD;
    const __half* Vg0 = v2t + (long)bh*HD*IMG_TOK;

    auto loadKV = [&](int st, int kb){
        const __half* Kg = Kg0 + (long)kb*64*HD;
        for(int idx = tid; idx < 576; idx += 256){
            int r = idx/9, c = idx%9;
            cp16(Ks + st*K_ST + r*QST + c*4, Kg + (long)r*HD + c*8, 16);
        }
        const __half* Vg = Vg0 + kb*64;
        for(int idx = tid; idx < 576; idx += 256){
            int r = idx/8, c = idx%8;
            cp16(Vs + st*V_ST + r*VST + c*4, Vg + (long)r*IMG_TOK + c*8, 16);
        }
    };

    for(int idx = tid; idx < 3*64*4; idx += 256){
        int st = idx/256, rem = idx%256, r = rem>>2, c = rem&3;
        Ks[st*K_ST + r*QST + 36 + c] = 0;
    }
    const __half* Qg = q2 + ((long)bh*IMG_TOK + qb*128)*HD;
    for(int idx = tid; idx < 128*40; idx += 256){
        int r = idx/40, c = idx%40;
        Qs[r*QST + c] = (c < 36) ? *(const uint32_t*)(Qg + (long)r*HD + 2*c) : 0u;
    }

    loadKV(0, 0); CP_COMMIT();
    loadKV(1, 1); CP_COMMIT();
    __syncthreads();

    uint32_t qf[5][4];
    #pragma unroll
    for(int s=0;s<5;s++){
        qf[s][0] = Qs[(w*16+g  )*QST + s*8 + tq    ];
        qf[s][1] = Qs[(w*16+8+g)*QST + s*8 + tq    ];
        qf[s][2] = Qs[(w*16+g  )*QST + s*8 + tq + 4];
        qf[s][3] = Qs[(w*16+8+g)*QST + s*8 + tq + 4];
    }

    float m0 = -3.4e38f, m1 = -3.4e38f, l0 = 0.f, l1 = 0.f;
    float o[9][4];
    #pragma unroll
    for(int nt=0;nt<9;nt++){ o[nt][0]=0.f; o[nt][1]=0.f; o[nt][2]=0.f; o[nt][3]=0.f; }

    for(int kb=0; kb<16; kb++){
        if(kb+1 < 16){ CP_WAIT1(); } else { CP_WAIT0(); }
        __syncthreads();

        const uint32_t* Kst = Ks + (kb%3)*K_ST;
        const uint32_t* Vst = Vs + (kb%3)*V_ST;

        float sacc[8][4];
        #pragma unroll
        for(int nt=0;nt<8;nt++){ sacc[nt][0]=0.f; sacc[nt][1]=0.f; sacc[nt][2]=0.f; sacc[nt][3]=0.f; }
        #pragma unroll
        for(int s=0;s<5;s++){
            #pragma unroll
            for(int nt=0;nt<8;nt++){
                uint32_t bf[2];
                bf[0] = Kst[(nt*8+g)*QST + s*8 + tq    ];
                bf[1] = Kst[(nt*8+g)*QST + s*8 + tq + 4];
                mma16(sacc[nt], qf[s], bf);
            }
        }

        float rm0 = -3.4e38f, rm1 = -3.4e38f;
        #pragma unroll
        for(int nt=0;nt<8;nt++){
            rm0 = fmaxf(rm0, fmaxf(sacc[nt][0], sacc[nt][1]));
            rm1 = fmaxf(rm1, fmaxf(sacc[nt][2], sacc[nt][3]));
        }
        rm0 = fmaxf(rm0, __shfl_xor_sync(0xffffffffu, rm0, 1));
        rm0 = fmaxf(rm0, __shfl_xor_sync(0xffffffffu, rm0, 2));
        rm1 = fmaxf(rm1, __shfl_xor_sync(0xffffffffu, rm1, 1));
        rm1 = fmaxf(rm1, __shfl_xor_sync(0xffffffffu, rm1, 2));

        float m0n = fmaxf(m0, rm0), m1n = fmaxf(m1, rm1);
        float a0 = __expf(m0 - m0n), a1 = __expf(m1 - m1n);
        m0 = m0n; m1 = m1n;

        float rs0 = 0.f, rs1 = 0.f;
        #pragma unroll
        for(int nt=0;nt<8;nt++){
            sacc[nt][0] = __expf(sacc[nt][0] - m0n);
            sacc[nt][1] = __expf(sacc[nt][1] - m0n);
            sacc[nt][2] = __expf(sacc[nt][2] - m1n);
            sacc[nt][3] = __expf(sacc[nt][3] - m1n);
            rs0 += sacc[nt][0] + sacc[nt][1];
            rs1 += sacc[nt][2] + sacc[nt][3];
        }
        rs0 += __shfl_xor_sync(0xffffffffu, rs0, 1);
        rs0 += __shfl_xor_sync(0xffffffffu, rs0, 2);
        rs1 += __shfl_xor_sync(0xffffffffu, rs1, 1);
        rs1 += __shfl_xor_sync(0xffffffffu, rs1, 2);
        l0 = l0*a0 + rs0;
        l1 = l1*a1 + rs1;

        #pragma unroll
        for(int nt=0;nt<9;nt++){
            o[nt][0]*=a0; o[nt][1]*=a0; o[nt][2]*=a1; o[nt][3]*=a1;
        }

        #pragma unroll
        for(int ks=0;ks<4;ks++){
            uint32_t pf[4];
            pf[0] = h2u(sacc[2*ks  ][0], sacc[2*ks  ][1]);
            pf[1] = h2u(sacc[2*ks  ][2], sacc[2*ks  ][3]);
            pf[2] = h2u(sacc[2*ks+1][0], sacc[2*ks+1][1]);
            pf[3] = h2u(sacc[2*ks+1][2], sacc[2*ks+1][3]);
            #pragma unroll
            for(int nt=0;nt<9;nt++){
                uint32_t bf[2];
                bf[0] = Vst[(nt*8+g)*VST + ks*8 + tq    ];
                bf[1] = Vst[(nt*8+g)*VST + ks*8 + tq + 4];
                mma16(o[nt], pf, bf);
            }
        }

        if(kb+2 < 16){ loadKV((kb+2)%3, kb+2); CP_COMMIT(); }
    }

    float inv0 = 1.f/l0, inv1 = 1.f/l1;
    int b = bh >> 4, h = bh & 15;
    int t0 = qb*128 + w*16 + g;
    long base0 = (long)(b*IMG_TOK + t0    )*HIDDEN + h*HD;
    long base1 = (long)(b*IMG_TOK + t0 + 8)*HIDDEN + h*HD;
    #pragma unroll
    for(int nt=0;nt<9;nt++){
        int col = nt*8 + tq*2;
        *(__half2*)(attn + base0 + col) = __floats2half2_rn(o[nt][0]*inv0, o[nt][1]*inv0);
        *(__half2*)(attn + base1 + col) = __floats2half2_rn(o[nt][2]*inv1, o[nt][3]*inv1);
    }
}

// ---------------- LayerNorm (fp32 in, fp16 out; vectorized) ----------------
__global__ void ln_kernel(const float* __restrict__ x, const float* __restrict__ g,
                          const float* __restrict__ b, __half* __restrict__ y, int N)
{
    __shared__ float sh[32];
    const int n4 = N >> 2;
    const float4* X4 = (const float4*)(x + (long)blockIdx.x * N);
    const float4* G4 = (const float4*)g;
    const float4* B4 = (const float4*)b;
    __half2* Y2 = (__half2*)(y + (long)blockIdx.x * N);

    float s=0.f, ss=0.f;
    for(int c=threadIdx.x;c<n4;c+=blockDim.x){
        float4 v = X4[c];
        s  += v.x + v.y + v.z + v.w;
        ss += v.x*v.x + v.y*v.y + v.z*v.z + v.w*v.w;
    }
    s  = blockReduceSum(s,  sh);
    ss = blockReduceSum(ss, sh);
    float mu  = s  / (float)N;
    float var = ss / (float)N - mu*mu;
    float rs  = rsqrtf(var + 1e-6f);
    for(int c=threadIdx.x;c<n4;c+=blockDim.x){
        float4 v = X4[c];
        float4 gg = G4[c], bb = B4[c];
        Y2[2*c  ] = __floats2half2_rn((v.x-mu)*rs*gg.x + bb.x, (v.y-mu)*rs*gg.y + bb.y);
        Y2[2*c+1] = __floats2half2_rn((v.z-mu)*rs*gg.z + bb.z, (v.w-mu)*rs*gg.w + bb.w);
    }
}

// ---------------- RoPE tables ----------------
__global__ void init_rope()
{
    int gid = blockIdx.x*blockDim.x + threadIdx.x;
    if(gid >= IMG_TOK*HD) return;
    int d = gid % HD, tt = gid / HD;
    int iw=tt&1, ih=(tt>>1)&1, bw=(tt>>2)&15, bh=tt>>6;
    int gh = bh*2+ih, gw = bw*2+iw;
    int dd = d % 36;
    int pos, i;
    if(dd < 18){ i = dd;      pos = gh; }
    else       { i = dd - 18; pos = gw; }
    float inv = powf(10000.0f, -((float)(2*i)/36.0f));
    float ang = (float)pos * inv;
    g_cos[gid] = cosf(ang);
    g_sin[gid] = sinf(ang);
}

// ---------------- pos-embed bilinear add ----------------
__global__ void add_pos(float* __restrict__ x, const float* __restrict__ pe)
{
    int gid = blockIdx.x*blockDim.x + threadIdx.x;
    if(gid >= SEQ*HIDDEN) return;
    int j = gid % HIDDEN; int s = gid / HIDDEN;
    int tt = s & 1023;
    int iw=tt&1, ih=(tt>>1)&1, bw=(tt>>2)&15, bh=tt>>6;
    int gh = bh*2+ih, gw = bw*2+iw;
    double hl = (double)gh*47.0/31.0;
    double wl = (double)gw*47.0/31.0;
    int h0=(int)hl; int h1=min(h0+1,47); float dh=(float)(hl-(double)h0);
    int w0=(int)wl; int w1=min(w0+1,47); float dw=(float)(wl-(double)w0);
    float p00 = pe[(h0*48+w0)*HIDDEN + j];
    float p01 = pe[(h0*48+w1)*HIDDEN + j];
    float p10 = pe[(h1*48+w0)*HIDDEN + j];
    float p11 = pe[(h1*48+w1)*HIDDEN + j];
    float v = (1.f-dh)*((1.f-dw)*p00 + dw*p01) + dh*((1.f-dw)*p10 + dw*p11);
    x[gid] += v;
}

// ---------------- fused RoPE(Q,K) + V transpose ----------------
__global__ void rope_pack2(const __half* __restrict__ qkv, __half* __restrict__ q2,
                           __half* __restrict__ k2, __half* __restrict__ v16t)
{
    __shared__ __half tile[64][80];
    const int tb = blockIdx.x, bh = blockIdx.y;
    const int b = bh >> 4, h = bh & 15;
    const int tid = threadIdx.x;

    for(int idx = tid; idx < 64*HD; idx += 256){
        int r = idx / HD, d = idx % HD;
        int tt = tb*64 + r;
        long base = (long)(b*IMG_TOK + tt)*(3*HIDDEN) + h*HD;
        float c  = g_cos[tt*HD + d];
        float sn = g_sin[tt*HD + d];
        float qd = __half2float(qkv[base + d]);
        float kd = __half2float(qkv[base + HIDDEN + d]);
        int   dp  = (d<36) ? d+36 : d-36;
        float sgn = (d<36) ? -1.f : 1.f;
        float qp = __half2float(qkv[base + dp]);
        float kp = __half2float(qkv[base + HIDDEN + dp]);
        long oi = ((long)bh*IMG_TOK + tt)*HD + d;
        q2[oi] = __float2half((qd*c + sgn*qp*sn) * SCALE_Q);
        k2[oi] = __float2half( kd*c + sgn*kp*sn);
        tile[r][d] = qkv[base + 2*HIDDEN + d];
    }
    __syncthreads();
    for(int idx = tid; idx < HD*64; idx += 256){
        int rr = idx / 64, cc = idx % 64;
        v16t[((long)bh*HD + rr)*IMG_TOK + tb*64 + cc] = tile[cc][rr];
    }
}

// ---------------- host helpers ----------------
static inline void gemma(const __half*A,const __half*B,void*C,const float*bias,const float*res,
                         int M,int N,int K,int flags){
    dim3 g((N+127)/128, M/256);
    gemm_a<<<g,512,GSMEM>>>(A,B,C,bias,res,M,N,K,flags);
}

extern "C" void kernel_launch(void* const* d_in, const int* in_sizes, int n_in,
                              void* d_out, int out_size)
{
    const float* pixel   = (const float*)d_in[0];
    const float* patch_w = (const float*)d_in[1];
    const float* patch_b = (const float*)d_in[2];
    const float* pos_e   = (const float*)d_in[3];
    const float* qkv_w   = (const float*)d_in[4];
    const float* qkv_b   = (const float*)d_in[5];
    const float* proj_w  = (const float*)d_in[6];
    const float* proj_b  = (const float*)d_in[7];
    const float* ln1_g   = (const float*)d_in[8];
    const float* ln1_b   = (const float*)d_in[9];
    const float* ln2_g   = (const float*)d_in[10];
    const float* ln2_b   = (const float*)d_in[11];
    const float* fc1_w   = (const float*)d_in[12];
    const float* fc1_b   = (const float*)d_in[13];
    const float* fc2_w   = (const float*)d_in[14];
    const float* fc2_b   = (const float*)d_in[15];
    const float* m_ln_g  = (const float*)d_in[16];
    const float* m_ln_b  = (const float*)d_in[17];
    const float* m_fc1_w = (const float*)d_in[18];
    const float* m_fc1_b = (const float*)d_in[19];
    const float* m_fc2_w = (const float*)d_in[20];
    const float* m_fc2_b = (const float*)d_in[21];
    const float* ds_ln_g = (const float*)d_in[22];
    const float* ds_ln_b = (const float*)d_in[23];
    const float* ds_fc1_w= (const float*)d_in[24];
    const float* ds_fc1_b= (const float*)d_in[25];
    const float* ds_fc2_w= (const float*)d_in[26];
    const float* ds_fc2_b= (const float*)d_in[27];
    float* out = (float*)d_out;

    cudaFuncSetAttribute(gemm_a, cudaFuncAttributeMaxDynamicSharedMemorySize, GSMEM);
    cudaFuncSetAttribute(flash_attn, cudaFuncAttributeMaxDynamicSharedMemorySize, FSMEM);

    float *px;
    __half *pw16,*pqw16,*ppw16,*pf1w16,*pf2w16,*pm1w16,*pm2w16,*pd1w16,*pd2w16,*ppx16;
    __half *pxn16,*pqkv16,*pq16,*pk16,*pv16t,*pat16,*ph16,*pmh16,*pmf16;
    cudaGetSymbolAddress((void**)&px,    g_x);
    cudaGetSymbolAddress((void**)&pw16,  w16_patch);
    cudaGetSymbolAddress((void**)&pqw16, w16_qkv);
    cudaGetSymbolAddress((void**)&ppw16, w16_proj);
    cudaGetSymbolAddress((void**)&pf1w16,w16_fc1);
    cudaGetSymbolAddress((void**)&pf2w16,w16_fc2);
    cudaGetSymbolAddress((void**)&pm1w16,w16_mfc1);
    cudaGetSymbolAddress((void**)&pm2w16,w16_mfc2);
    cudaGetSymbolAddress((void**)&pd1w16,w16_dfc1);
    cudaGetSymbolAddress((void**)&pd2w16,w16_dfc2);
    cudaGetSymbolAddress((void**)&ppx16, g_px16);
    cudaGetSymbolAddress((void**)&pxn16, g_xn16);
    cudaGetSymbolAddress((void**)&pqkv16,g_qkv16);
    cudaGetSymbolAddress((void**)&pq16,  g_q16);
    cudaGetSymbolAddress((void**)&pk16,  g_k16);
    cudaGetSymbolAddress((void**)&pv16t, g_v16t);
    cudaGetSymbolAddress((void**)&pat16, g_at16);
    cudaGetSymbolAddress((void**)&ph16,  g_h16);
    cudaGetSymbolAddress((void**)&pmh16, g_mh16);
    cudaGetSymbolAddress((void**)&pmf16, g_mf16);

    const int EW = 256;
    init_rope<<<(IMG_TOK*HD + EW-1)/EW, EW>>>();

    auto F2H = [&](const float* s, __half* d, long n){
        long n4 = n/4;
        int grid = (int)((n4 + 255)/256); if(grid > 4096) grid = 4096;
        f2h<<<grid, 256>>>((const float4*)s, (__half2*)d, n4);
    };
    F2H(pixel,    ppx16,  (long)SEQ*PATCHD);
    F2H(patch_w,  pw16,   (long)HIDDEN*PATCHD);
    F2H(qkv_w,    pqw16,  (long)DEPTH*3*HIDDEN*HIDDEN);
    F2H(proj_w,   ppw16,  (long)DEPTH*HIDDEN*HIDDEN);
    F2H(fc1_w,    pf1w16, (long)DEPTH*INTER*HIDDEN);
    F2H(fc2_w,    pf2w16, (long)DEPTH*HIDDEN*INTER);
    F2H(m_fc1_w,  pm1w16, (long)MERGED*MERGED);
    F2H(m_fc2_w,  pm2w16, (long)OUTH*MERGED);
    F2H(ds_fc1_w, pd1w16, (long)2*MERGED*MERGED);
    F2H(ds_fc2_w, pd2w16, (long)2*OUTH*MERGED);

    gemma(ppx16, pw16, px, patch_b, nullptr, SEQ, HIDDEN, PATCHD, 0);
    add_pos<<<(SEQ*HIDDEN + EW-1)/EW, EW>>>(px, pos_e);

    for(int i=0;i<DEPTH;i++){
        ln_kernel<<<SEQ,256>>>(px, ln1_g+(long)i*HIDDEN, ln1_b+(long)i*HIDDEN, pxn16, HIDDEN);
        gemma(pxn16, pqw16+(long)i*3*HIDDEN*HIDDEN, pqkv16, qkv_b+(long)i*3*HIDDEN, nullptr,
              SEQ, 3*HIDDEN, HIDDEN, 2);
        rope_pack2<<<dim3(16, NBH), 256>>>(pqkv16, pq16, pk16, pv16t);
        flash_attn<<<dim3(8, NBH), 256, FSMEM>>>(pq16, pk16, pv16t, pat16);
        gemma(pat16, ppw16+(long)i*HIDDEN*HIDDEN, px, proj_b+(long)i*HIDDEN, px,
              SEQ, HIDDEN, HIDDEN, 0);

        ln_kernel<<<SEQ,256>>>(px, ln2_g+(long)i*HIDDEN, ln2_b+(long)i*HIDDEN, pxn16, HIDDEN);
        gemma(pxn16, pf1w16+(long)i*INTER*HIDDEN, ph16, fc1_b+(long)i*INTER, nullptr,
              SEQ, INTER, HIDDEN, 1|2);
        gemma(ph16, pf2w16+(long)i*HIDDEN*INTER, px, fc2_b+(long)i*HIDDEN, px,
              SEQ, HIDDEN, INTER, 0);

        if(i==2 || i==4){
            int j = (i==2) ? 0 : 1;
            ln_kernel<<<1024,256>>>(px, ds_ln_g+(long)j*MERGED, ds_ln_b+(long)j*MERGED, pmh16, MERGED);
            gemma(pmh16, pd1w16+(long)j*MERGED*MERGED, pmf16, ds_fc1_b+(long)j*MERGED, nullptr,
                  1024, MERGED, MERGED, 1|2);
            gemma(pmf16, pd2w16+(long)j*OUTH*MERGED, out+(long)(1+j)*1024*OUTH,
                  ds_fc2_b+(long)j*OUTH, nullptr,
                  1024, OUTH, MERGED, 0);
        }
    }

    ln_kernel<<<SEQ,256>>>(px, m_ln_g, m_ln_b, pmh16, HIDDEN);
    gemma(pmh16, pm1w16, pmf16, m_fc1_b, nullptr, 1024, MERGED, MERGED, 1|2);
    gemma(pmf16, pm2w16, out, m_fc2_b, nullptr, 1024, OUTH, MERGED, 0);
}

// round 15
// speedup vs baseline: 1.0608x; 1.0608x over previous
#include <cuda_runtime.h>
#include <cuda_fp16.h>
#include <math.h>
#include <stdint.h>

// ---------------- problem constants ----------------
#define SEQ      4096
#define HIDDEN   1152
#define HEADS    16
#define HD       72
#define INTER    4304
#define DEPTH    6
#define MERGED   4608
#define OUTH     2048
#define PATCHD   1536
#define IMG_TOK  1024
#define NBH      64
#define SCALE_Q  0.11785113019775793f

// ---------------- device scratch ----------------
__device__ __half w16_patch[HIDDEN*PATCHD];
__device__ __half w16_qkv [DEPTH*3*HIDDEN*HIDDEN];
__device__ __half w16_proj[DEPTH*HIDDEN*HIDDEN];
__device__ __half w16_fc1 [DEPTH*INTER*HIDDEN];
__device__ __half w16_fc2 [DEPTH*HIDDEN*INTER];
__device__ __half w16_mfc1[MERGED*MERGED];
__device__ __half w16_mfc2[OUTH*MERGED];
__device__ __half w16_dfc1[2*MERGED*MERGED];
__device__ __half w16_dfc2[2*OUTH*MERGED];
__device__ __half g_px16  [SEQ*PATCHD];
__device__ __half g_xn16  [SEQ*HIDDEN];
__device__ __half g_qkv16 [SEQ*3*HIDDEN];
__device__ __half g_q16   [NBH*IMG_TOK*HD];
__device__ __half g_k16   [NBH*IMG_TOK*HD];
__device__ __half g_v16t  [NBH*HD*IMG_TOK];
__device__ __half g_at16  [SEQ*HIDDEN];
__device__ __half g_h16   [SEQ*INTER];
__device__ __half g_mh16  [SEQ*HIDDEN];
__device__ __half g_mf16  [1024*MERGED];
__device__ __half g_dh16  [2][1024*MERGED];
__device__ __half g_df16  [2][1024*MERGED];
__device__ float g_x   [SEQ*HIDDEN];
__device__ float g_cos [IMG_TOK*HD];
__device__ float g_sin [IMG_TOK*HD];

// ---------------- helpers ----------------
__device__ __forceinline__ float gelu_f(float x){
    float x3 = x*x*x;
    return 0.5f*x*(1.0f + tanhf(0.7978845608028654f*(x + 0.044715f*x3)));
}
__device__ __forceinline__ uint32_t h2u(float a, float b){
    __half2 h = __floats2half2_rn(a, b);
    return *(uint32_t*)&h;
}
__device__ __forceinline__ void mma16(float* c, const uint32_t* a, const uint32_t* b){
    asm volatile("mma.sync.aligned.m16n8k16.row.col.f32.f16.f16.f32 "
        "{%0,%1,%2,%3},{%4,%5,%6,%7},{%8,%9},{%0,%1,%2,%3};"
        : "+f"(c[0]),"+f"(c[1]),"+f"(c[2]),"+f"(c[3])
        : "r"(a[0]),"r"(a[1]),"r"(a[2]),"r"(a[3]),"r"(b[0]),"r"(b[1]));
}
#define LDSM4(r, addr) \
    asm volatile("ldmatrix.sync.aligned.m8n8.x4.shared.b16 {%0,%1,%2,%3}, [%4];" \
        : "=r"((r)[0]),"=r"((r)[1]),"=r"((r)[2]),"=r"((r)[3]) : "r"(addr))
__device__ __forceinline__ void cp16(void* dst, const void* src, int nbytes){
    asm volatile("cp.async.cg.shared.global [%0], [%1], 16, %2;"
        :: "r"((uint32_t)__cvta_generic_to_shared(dst)), "l"(src), "r"(nbytes) : "memory");
}
#define CP_COMMIT() asm volatile("cp.async.commit_group;" ::: "memory")
#define CP_WAIT1()  asm volatile("cp.async.wait_group 1;" ::: "memory")
#define CP_WAIT0()  asm volatile("cp.async.wait_group 0;" ::: "memory")

__device__ __forceinline__ float blockReduceSum(float v, float* sh){
    int tid = threadIdx.x;
    __syncthreads();
    #pragma unroll
    for(int o=16;o>0;o>>=1) v += __shfl_xor_sync(0xffffffffu, v, o);
    if((tid&31)==0) sh[tid>>5] = v;
    __syncthreads();
    if(tid < 32){
        float r = (tid < (int)(blockDim.x>>5)) ? sh[tid] : 0.f;
        #pragma unroll
        for(int o=16;o>0;o>>=1) r += __shfl_xor_sync(0xffffffffu, r, o);
        if(tid==0) sh[0] = r;
    }
    __syncthreads();
    return sh[0];
}

// ---------------- vectorized fp32 -> fp16 ----------------
__global__ void f2h(const float4* __restrict__ s, __half2* __restrict__ d, long n4){
    long i = (long)blockIdx.x*blockDim.x + threadIdx.x;
    long stride = (long)gridDim.x*blockDim.x;
    for(; i<n4; i+=stride){
        float4 v = s[i];
        d[2*i  ] = __floats2half2_rn(v.x, v.y);
        d[2*i+1] = __floats2half2_rn(v.z, v.w);
    }
}

// ---------------- fp16 GEMM: 128x128, K-chunk 64, 3-stage, 1 barrier/iter (R13) ----------------
#define GST 72
#define A_ST  (128*GST)
#define GSMEM (6*A_ST*2)       // 110592 bytes

__global__ __launch_bounds__(256,2)
void gemm_a(const __half* __restrict__ A, const __half* __restrict__ B,
            void* __restrict__ Cv, const float* __restrict__ bias,
            const float* __restrict__ res,
            int M, int N, int K, int flags)
{
    extern __shared__ __half smh[];
    __half* As = smh;
    __half* Bs = smh + 3*A_ST;

    const int tid  = threadIdx.x;
    const int lane = tid & 31, warp = tid >> 5;
    const int g = lane >> 2, tq = lane & 3;
    const int wm = warp >> 1, wn = warp & 1;
    const int m0 = wm*32, n0 = wn*64;
    const int bn = blockIdx.x, bm = blockIdx.y;

    float acc[2][8][4];
    #pragma unroll
    for(int i=0;i<2;i++)
        #pragma unroll
        for(int j=0;j<8;j++)
            #pragma unroll
            for(int q=0;q<4;q++) acc[i][j][q]=0.f;

    const int NT = (K+63)/64;
    const int lr  = tid >> 3;
    const int seg = tid & 7;

    auto loadStage = [&](int st, int k0){
        int kh  = k0 + seg*8;
        int nb  = (K - kh)*2; nb = nb < 0 ? 0 : (nb > 16 ? 16 : nb);
        int khc = kh < K ? kh : 0;
        #pragma unroll
        for(int i=0;i<4;i++){
            int row = lr + i*32;
            cp16(As + st*A_ST + row*GST + seg*8,
                 A + (long)(bm*128+row)*K + khc, nb);
            int brow = bn*128 + row;
            cp16(Bs + st*A_ST + row*GST + seg*8,
                 B + (long)(brow < N ? brow : 0)*K + khc, brow < N ? nb : 0);
        }
    };

    loadStage(0, 0); CP_COMMIT();
    if(NT > 1){ loadStage(1, 64); CP_COMMIT(); }

    for(int kt=0; kt<NT; kt++){
        if(kt+1 < NT){ CP_WAIT1(); } else { CP_WAIT0(); }
        __syncthreads();

        const int st = kt % 3;
        const uint32_t abase = (uint32_t)__cvta_generic_to_shared(As + st*A_ST);
        const uint32_t bbase = (uint32_t)__cvta_generic_to_shared(Bs + st*A_ST);
        const int lrow = lane & 15, lcol = (lane >> 4) * 8;
        #pragma unroll
        for(int s=0;s<4;s++){
            uint32_t af[2][4];
            #pragma unroll
            for(int mt=0;mt<2;mt++){
                uint32_t ad = abase + ((m0 + mt*16 + lrow)*GST + s*16 + lcol)*2;
                LDSM4(af[mt], ad);
            }
            uint32_t bq[4][4];
            #pragma unroll
            for(int p=0;p<4;p++){
                uint32_t bd = bbase + ((n0 + p*16 + lrow)*GST + s*16 + lcol)*2;
                LDSM4(bq[p], bd);
            }
            #pragma unroll
            for(int mt=0;mt<2;mt++)
                #pragma unroll
                for(int nt=0;nt<8;nt++){
                    uint32_t bf[2] = { bq[nt>>1][nt&1], bq[nt>>1][2+(nt&1)] };
                    mma16(acc[mt][nt], af[mt], bf);
                }
        }
        if(kt+2 < NT){ loadStage((kt+2)%3, (kt+2)*64); CP_COMMIT(); }
    }

    const int dogelu = flags & 1, out16 = flags & 2;
    float* Cf = (float*)Cv;
    __half* Ch = (__half*)Cv;
    #pragma unroll
    for(int mt=0;mt<2;mt++){
        int r0 = bm*128 + m0 + mt*16 + g;
        int r1 = r0 + 8;
        #pragma unroll
        for(int nt=0;nt<8;nt++){
            int col = bn*128 + n0 + nt*8 + tq*2;
            if(col < N){
                float v0 = acc[mt][nt][0], v1 = acc[mt][nt][1];
                float v2 = acc[mt][nt][2], v3 = acc[mt][nt][3];
                if(bias){ float b0=bias[col], b1=bias[col+1]; v0+=b0; v1+=b1; v2+=b0; v3+=b1; }
                if(dogelu){ v0=gelu_f(v0); v1=gelu_f(v1); v2=gelu_f(v2); v3=gelu_f(v3); }
                long i0 = (long)r0*N + col, i1 = (long)r1*N + col;
                if(out16){
                    *(__half2*)(Ch + i0) = __floats2half2_rn(v0, v1);
                    *(__half2*)(Ch + i1) = __floats2half2_rn(v2, v3);
                } else {
                    if(res){ v0+=res[i0]; v1+=res[i0+1]; v2+=res[i1]; v3+=res[i1+1]; }
                    Cf[i0]=v0; Cf[i0+1]=v1; Cf[i1]=v2; Cf[i1+1]=v3;
                }
            }
        }
    }
}

// ---------------- fused flash attention: 3-stage cp.async K/V pipeline ----------------
#define QST 44
#define VST 36
#define K_ST (64*QST)
#define V_ST (72*VST)
#define FSMEM ((128*QST + 3*K_ST + 3*V_ST)*4)   // 87424 bytes

__global__ __launch_bounds__(256,2)
void flash_attn(const __half* __restrict__ q2, const __half* __restrict__ k2,
                const __half* __restrict__ v2t, __half* __restrict__ attn)
{
    extern __shared__ uint32_t fsm[];
    uint32_t* Qs = fsm;
    uint32_t* Ks = fsm + 128*QST;
    uint32_t* Vs = Ks + 3*K_ST;

    const int tid = threadIdx.x;
    const int lane = tid & 31, w = tid >> 5;
    const int g = lane >> 2, tq = lane & 3;
    const int qb = blockIdx.x, bh = blockIdx.y;

    const __half* Kg0 = k2  + (long)bh*IMG_TOK*HD;
    const __half* Vg0 = v2t + (long)bh*HD*IMG_TOK;

    auto loadKV = [&](int st, int kb){
        const __half* Kg = Kg0 + (long)kb*64*HD;
        for(int idx = tid; idx < 576; idx += 256){
            int r = idx/9, c = idx%9;
            cp16(Ks + st*K_ST + r*QST + c*4, Kg + (long)r*HD + c*8, 16);
        }
        const __half* Vg = Vg0 + kb*64;
        for(int idx = tid; idx < 576; idx += 256){
            int r = idx/8, c = idx%8;
            cp16(Vs + st*V_ST + r*VST + c*4, Vg + (long)r*IMG_TOK + c*8, 16);
        }
    };

    for(int idx = tid; idx < 3*64*4; idx += 256){
        int st = idx/256, rem = idx%256, r = rem>>2, c = rem&3;
        Ks[st*K_ST + r*QST + 36 + c] = 0;
    }
    const __half* Qg = q2 + ((long)bh*IMG_TOK + qb*128)*HD;
    for(int idx = tid; idx < 128*40; idx += 256){
        int r = idx/40, c = idx%40;
        Qs[r*QST + c] = (c < 36) ? *(const uint32_t*)(Qg + (long)r*HD + 2*c) : 0u;
    }

    loadKV(0, 0); CP_COMMIT();
    loadKV(1, 1); CP_COMMIT();
    __syncthreads();

    uint32_t qf[5][4];
    #pragma unroll
    for(int s=0;s<5;s++){
        qf[s][0] = Qs[(w*16+g  )*QST + s*8 + tq    ];
        qf[s][1] = Qs[(w*16+8+g)*QST + s*8 + tq    ];
        qf[s][2] = Qs[(w*16+g  )*QST + s*8 + tq + 4];
        qf[s][3] = Qs[(w*16+8+g)*QST + s*8 + tq + 4];
    }

    float m0 = -3.4e38f, m1 = -3.4e38f, l0 = 0.f, l1 = 0.f;
    float o[9][4];
    #pragma unroll
    for(int nt=0;nt<9;nt++){ o[nt][0]=0.f; o[nt][1]=0.f; o[nt][2]=0.f; o[nt][3]=0.f; }

    for(int kb=0; kb<16; kb++){
        if(kb+1 < 16){ CP_WAIT1(); } else { CP_WAIT0(); }
        __syncthreads();

        const uint32_t* Kst = Ks + (kb%3)*K_ST;
        const uint32_t* Vst = Vs + (kb%3)*V_ST;

        float sacc[8][4];
        #pragma unroll
        for(int nt=0;nt<8;nt++){ sacc[nt][0]=0.f; sacc[nt][1]=0.f; sacc[nt][2]=0.f; sacc[nt][3]=0.f; }
        #pragma unroll
        for(int s=0;s<5;s++){
            #pragma unroll
            for(int nt=0;nt<8;nt++){
                uint32_t bf[2];
                bf[0] = Kst[(nt*8+g)*QST + s*8 + tq    ];
                bf[1] = Kst[(nt*8+g)*QST + s*8 + tq + 4];
                mma16(sacc[nt], qf[s], bf);
            }
        }

        float rm0 = -3.4e38f, rm1 = -3.4e38f;
        #pragma unroll
        for(int nt=0;nt<8;nt++){
            rm0 = fmaxf(rm0, fmaxf(sacc[nt][0], sacc[nt][1]));
            rm1 = fmaxf(rm1, fmaxf(sacc[nt][2], sacc[nt][3]));
        }
        rm0 = fmaxf(rm0, __shfl_xor_sync(0xffffffffu, rm0, 1));
        rm0 = fmaxf(rm0, __shfl_xor_sync(0xffffffffu, rm0, 2));
        rm1 = fmaxf(rm1, __shfl_xor_sync(0xffffffffu, rm1, 1));
        rm1 = fmaxf(rm1, __shfl_xor_sync(0xffffffffu, rm1, 2));

        float m0n = fmaxf(m0, rm0), m1n = fmaxf(m1, rm1);
        float a0 = __expf(m0 - m0n), a1 = __expf(m1 - m1n);
        m0 = m0n; m1 = m1n;

        float rs0 = 0.f, rs1 = 0.f;
        #pragma unroll
        for(int nt=0;nt<8;nt++){
            sacc[nt][0] = __expf(sacc[nt][0] - m0n);
            sacc[nt][1] = __expf(sacc[nt][1] - m0n);
            sacc[nt][2] = __expf(sacc[nt][2] - m1n);
            sacc[nt][3] = __expf(sacc[nt][3] - m1n);
            rs0 += sacc[nt][0] + sacc[nt][1];
            rs1 += sacc[nt][2] + sacc[nt][3];
        }
        rs0 += __shfl_xor_sync(0xffffffffu, rs0, 1);
        rs0 += __shfl_xor_sync(0xffffffffu, rs0, 2);
        rs1 += __shfl_xor_sync(0xffffffffu, rs1, 1);
        rs1 += __shfl_xor_sync(0xffffffffu, rs1, 2);
        l0 = l0*a0 + rs0;
        l1 = l1*a1 + rs1;

        #pragma unroll
        for(int nt=0;nt<9;nt++){
            o[nt][0]*=a0; o[nt][1]*=a0; o[nt][2]*=a1; o[nt][3]*=a1;
        }

        #pragma unroll
        for(int ks=0;ks<4;ks++){
            uint32_t pf[4];
            pf[0] = h2u(sacc[2*ks  ][0], sacc[2*ks  ][1]);
            pf[1] = h2u(sacc[2*ks  ][2], sacc[2*ks  ][3]);
            pf[2] = h2u(sacc[2*ks+1][0], sacc[2*ks+1][1]);
            pf[3] = h2u(sacc[2*ks+1][2], sacc[2*ks+1][3]);
            #pragma unroll
            for(int nt=0;nt<9;nt++){
                uint32_t bf[2];
                bf[0] = Vst[(nt*8+g)*VST + ks*8 + tq    ];
                bf[1] = Vst[(nt*8+g)*VST + ks*8 + tq + 4];
                mma16(o[nt], pf, bf);
            }
        }

        if(kb+2 < 16){ loadKV((kb+2)%3, kb+2); CP_COMMIT(); }
    }

    float inv0 = 1.f/l0, inv1 = 1.f/l1;
    int b = bh >> 4, h = bh & 15;
    int t0 = qb*128 + w*16 + g;
    long base0 = (long)(b*IMG_TOK + t0    )*HIDDEN + h*HD;
    long base1 = (long)(b*IMG_TOK + t0 + 8)*HIDDEN + h*HD;
    #pragma unroll
    for(int nt=0;nt<9;nt++){
        int col = nt*8 + tq*2;
        *(__half2*)(attn + base0 + col) = __floats2half2_rn(o[nt][0]*inv0, o[nt][1]*inv0);
        *(__half2*)(attn + base1 + col) = __floats2half2_rn(o[nt][2]*inv1, o[nt][3]*inv1);
    }
}

// ---------------- LayerNorm (fp32 in, fp16 out; vectorized) ----------------
__global__ void ln_kernel(const float* __restrict__ x, const float* __restrict__ g,
                          const float* __restrict__ b, __half* __restrict__ y, int N)
{
    __shared__ float sh[32];
    const int n4 = N >> 2;
    const float4* X4 = (const float4*)(x + (long)blockIdx.x * N);
    const float4* G4 = (const float4*)g;
    const float4* B4 = (const float4*)b;
    __half2* Y2 = (__half2*)(y + (long)blockIdx.x * N);

    float s=0.f, ss=0.f;
    for(int c=threadIdx.x;c<n4;c+=blockDim.x){
        float4 v = X4[c];
        s  += v.x + v.y + v.z + v.w;
        ss += v.x*v.x + v.y*v.y + v.z*v.z + v.w*v.w;
    }
    s  = blockReduceSum(s,  sh);
    ss = blockReduceSum(ss, sh);
    float mu  = s  / (float)N;
    float var = ss / (float)N - mu*mu;
    float rs  = rsqrtf(var + 1e-6f);
    for(int c=threadIdx.x;c<n4;c+=blockDim.x){
        float4 v = X4[c];
        float4 gg = G4[c], bb = B4[c];
        Y2[2*c  ] = __floats2half2_rn((v.x-mu)*rs*gg.x + bb.x, (v.y-mu)*rs*gg.y + bb.y);
        Y2[2*c+1] = __floats2half2_rn((v.z-mu)*rs*gg.z + bb.z, (v.w-mu)*rs*gg.w + bb.w);
    }
}

// ---------------- RoPE tables ----------------
__global__ void init_rope()
{
    int gid = blockIdx.x*blockDim.x + threadIdx.x;
    if(gid >= IMG_TOK*HD) return;
    int d = gid % HD, tt = gid / HD;
    int iw=tt&1, ih=(tt>>1)&1, bw=(tt>>2)&15, bh=tt>>6;
    int gh = bh*2+ih, gw = bw*2+iw;
    int dd = d % 36;
    int pos, i;
    if(dd < 18){ i = dd;      pos = gh; }
    else       { i = dd - 18; pos = gw; }
    float inv = powf(10000.0f, -((float)(2*i)/36.0f));
    float ang = (float)pos * inv;
    g_cos[gid] = cosf(ang);
    g_sin[gid] = sinf(ang);
}

// ---------------- pos-embed bilinear add ----------------
__global__ void add_pos(float* __restrict__ x, const float* __restrict__ pe)
{
    int gid = blockIdx.x*blockDim.x + threadIdx.x;
    if(gid >= SEQ*HIDDEN) return;
    int j = gid % HIDDEN; int s = gid / HIDDEN;
    int tt = s & 1023;
    int iw=tt&1, ih=(tt>>1)&1, bw=(tt>>2)&15, bh=tt>>6;
    int gh = bh*2+ih, gw = bw*2+iw;
    double hl = (double)gh*47.0/31.0;
    double wl = (double)gw*47.0/31.0;
    int h0=(int)hl; int h1=min(h0+1,47); float dh=(float)(hl-(double)h0);
    int w0=(int)wl; int w1=min(w0+1,47); float dw=(float)(wl-(double)w0);
    float p00 = pe[(h0*48+w0)*HIDDEN + j];
    float p01 = pe[(h0*48+w1)*HIDDEN + j];
    float p10 = pe[(h1*48+w0)*HIDDEN + j];
    float p11 = pe[(h1*48+w1)*HIDDEN + j];
    float v = (1.f-dh)*((1.f-dw)*p00 + dw*p01) + dh*((1.f-dw)*p10 + dw*p11);
    x[gid] += v;
}

// ---------------- fused RoPE(Q,K) + V transpose ----------------
__global__ void rope_pack2(const __half* __restrict__ qkv, __half* __restrict__ q2,
                           __half* __restrict__ k2, __half* __restrict__ v16t)
{
    __shared__ __half tile[64][80];
    const int tb = blockIdx.x, bh = blockIdx.y;
    const int b = bh >> 4, h = bh & 15;
    const int tid = threadIdx.x;

    for(int idx = tid; idx < 64*HD; idx += 256){
        int r = idx / HD, d = idx % HD;
        int tt = tb*64 + r;
        long base = (long)(b*IMG_TOK + tt)*(3*HIDDEN) + h*HD;
        float c  = g_cos[tt*HD + d];
        float sn = g_sin[tt*HD + d];
        float qd = __half2float(qkv[base + d]);
        float kd = __half2float(qkv[base + HIDDEN + d]);
        int   dp  = (d<36) ? d+36 : d-36;
        float sgn = (d<36) ? -1.f : 1.f;
        float qp = __half2float(qkv[base + dp]);
        float kp = __half2float(qkv[base + HIDDEN + dp]);
        long oi = ((long)bh*IMG_TOK + tt)*HD + d;
        q2[oi] = __float2half((qd*c + sgn*qp*sn) * SCALE_Q);
        k2[oi] = __float2half( kd*c + sgn*kp*sn);
        tile[r][d] = qkv[base + 2*HIDDEN + d];
    }
    __syncthreads();
    for(int idx = tid; idx < HD*64; idx += 256){
        int rr = idx / 64, cc = idx % 64;
        v16t[((long)bh*HD + rr)*IMG_TOK + tb*64 + cc] = tile[cc][rr];
    }
}

// ---------------- host helpers ----------------
static inline void gemma_s(cudaStream_t st, const __half*A,const __half*B,void*C,
                           const float*bias,const float*res,
                           int M,int N,int K,int flags){
    dim3 g((N+127)/128, M/128);
    gemm_a<<<g,256,GSMEM,st>>>(A,B,C,bias,res,M,N,K,flags);
}
static inline void gemma(const __half*A,const __half*B,void*C,const float*bias,const float*res,
                         int M,int N,int K,int flags){
    gemma_s(0, A,B,C,bias,res,M,N,K,flags);
}

extern "C" void kernel_launch(void* const* d_in, const int* in_sizes, int n_in,
                              void* d_out, int out_size)
{
    const float* pixel   = (const float*)d_in[0];
    const float* patch_w = (const float*)d_in[1];
    const float* patch_b = (const float*)d_in[2];
    const float* pos_e   = (const float*)d_in[3];
    const float* qkv_w   = (const float*)d_in[4];
    const float* qkv_b   = (const float*)d_in[5];
    const float* proj_w  = (const float*)d_in[6];
    const float* proj_b  = (const float*)d_in[7];
    const float* ln1_g   = (const float*)d_in[8];
    const float* ln1_b   = (const float*)d_in[9];
    const float* ln2_g   = (const float*)d_in[10];
    const float* ln2_b   = (const float*)d_in[11];
    const float* fc1_w   = (const float*)d_in[12];
    const float* fc1_b   = (const float*)d_in[13];
    const float* fc2_w   = (const float*)d_in[14];
    const float* fc2_b   = (const float*)d_in[15];
    const float* m_ln_g  = (const float*)d_in[16];
    const float* m_ln_b  = (const float*)d_in[17];
    const float* m_fc1_w = (const float*)d_in[18];
    const float* m_fc1_b = (const float*)d_in[19];
    const float* m_fc2_w = (const float*)d_in[20];
    const float* m_fc2_b = (const float*)d_in[21];
    const float* ds_ln_g = (const float*)d_in[22];
    const float* ds_ln_b = (const float*)d_in[23];
    const float* ds_fc1_w= (const float*)d_in[24];
    const float* ds_fc1_b= (const float*)d_in[25];
    const float* ds_fc2_w= (const float*)d_in[26];
    const float* ds_fc2_b= (const float*)d_in[27];
    float* out = (float*)d_out;

    cudaFuncSetAttribute(gemm_a, cudaFuncAttributeMaxDynamicSharedMemorySize, GSMEM);
    cudaFuncSetAttribute(flash_attn, cudaFuncAttributeMaxDynamicSharedMemorySize, FSMEM);

    // side stream + events (created once; same captured ops every call)
    static cudaStream_t s_side = [](){ cudaStream_t t; cudaStreamCreate(&t); return t; }();
    static cudaEvent_t  s_fork0 = [](){ cudaEvent_t e; cudaEventCreateWithFlags(&e, cudaEventDisableTiming); return e; }();
    static cudaEvent_t  s_fork1 = [](){ cudaEvent_t e; cudaEventCreateWithFlags(&e, cudaEventDisableTiming); return e; }();
    static cudaEvent_t  s_join  = [](){ cudaEvent_t e; cudaEventCreateWithFlags(&e, cudaEventDisableTiming); return e; }();

    float *px;
    __half *pw16,*pqw16,*ppw16,*pf1w16,*pf2w16,*pm1w16,*pm2w16,*pd1w16,*pd2w16,*ppx16;
    __half *pxn16,*pqkv16,*pq16,*pk16,*pv16t,*pat16,*ph16,*pmh16,*pmf16,*pdh16,*pdf16;
    cudaGetSymbolAddress((void**)&px,    g_x);
    cudaGetSymbolAddress((void**)&pw16,  w16_patch);
    cudaGetSymbolAddress((void**)&pqw16, w16_qkv);
    cudaGetSymbolAddress((void**)&ppw16, w16_proj);
    cudaGetSymbolAddress((void**)&pf1w16,w16_fc1);
    cudaGetSymbolAddress((void**)&pf2w16,w16_fc2);
    cudaGetSymbolAddress((void**)&pm1w16,w16_mfc1);
    cudaGetSymbolAddress((void**)&pm2w16,w16_mfc2);
    cudaGetSymbolAddress((void**)&pd1w16,w16_dfc1);
    cudaGetSymbolAddress((void**)&pd2w16,w16_dfc2);
    cudaGetSymbolAddress((void**)&ppx16, g_px16);
    cudaGetSymbolAddress((void**)&pxn16, g_xn16);
    cudaGetSymbolAddress((void**)&pqkv16,g_qkv16);
    cudaGetSymbolAddress((void**)&pq16,  g_q16);
    cudaGetSymbolAddress((void**)&pk16,  g_k16);
    cudaGetSymbolAddress((void**)&pv16t, g_v16t);
    cudaGetSymbolAddress((void**)&pat16, g_at16);
    cudaGetSymbolAddress((void**)&ph16,  g_h16);
    cudaGetSymbolAddress((void**)&pmh16, g_mh16);
    cudaGetSymbolAddress((void**)&pmf16, g_mf16);
    cudaGetSymbolAddress((void**)&pdh16, g_dh16);
    cudaGetSymbolAddress((void**)&pdf16, g_df16);

    const int EW = 256;
    init_rope<<<(IMG_TOK*HD + EW-1)/EW, EW>>>();

    auto F2H = [&](const float* s, __half* d, long n){
        long n4 = n/4;
        int grid = (int)((n4 + 255)/256); if(grid > 4096) grid = 4096;
        f2h<<<grid, 256>>>((const float4*)s, (__half2*)d, n4);
    };
    F2H(pixel,    ppx16,  (long)SEQ*PATCHD);
    F2H(patch_w,  pw16,   (long)HIDDEN*PATCHD);
    F2H(qkv_w,    pqw16,  (long)DEPTH*3*HIDDEN*HIDDEN);
    F2H(proj_w,   ppw16,  (long)DEPTH*HIDDEN*HIDDEN);
    F2H(fc1_w,    pf1w16, (long)DEPTH*INTER*HIDDEN);
    F2H(fc2_w,    pf2w16, (long)DEPTH*HIDDEN*INTER);
    F2H(m_fc1_w,  pm1w16, (long)MERGED*MERGED);
    F2H(m_fc2_w,  pm2w16, (long)OUTH*MERGED);
    F2H(ds_fc1_w, pd1w16, (long)2*MERGED*MERGED);
    F2H(ds_fc2_w, pd2w16, (long)2*OUTH*MERGED);

    gemma(ppx16, pw16, px, patch_b, nullptr, SEQ, HIDDEN, PATCHD, 0);
    add_pos<<<(SEQ*HIDDEN + EW-1)/EW, EW>>>(px, pos_e);

    for(int i=0;i<DEPTH;i++){
        ln_kernel<<<SEQ,256>>>(px, ln1_g+(long)i*HIDDEN, ln1_b+(long)i*HIDDEN, pxn16, HIDDEN);
        gemma(pxn16, pqw16+(long)i*3*HIDDEN*HIDDEN, pqkv16, qkv_b+(long)i*3*HIDDEN, nullptr,
              SEQ, 3*HIDDEN, HIDDEN, 2);
        rope_pack2<<<dim3(16, NBH), 256>>>(pqkv16, pq16, pk16, pv16t);
        flash_attn<<<dim3(8, NBH), 256, FSMEM>>>(pq16, pk16, pv16t, pat16);
        gemma(pat16, ppw16+(long)i*HIDDEN*HIDDEN, px, proj_b+(long)i*HIDDEN, px,
              SEQ, HIDDEN, HIDDEN, 0);

        ln_kernel<<<SEQ,256>>>(px, ln2_g+(long)i*HIDDEN, ln2_b+(long)i*HIDDEN, pxn16, HIDDEN);
        gemma(pxn16, pf1w16+(long)i*INTER*HIDDEN, ph16, fc1_b+(long)i*INTER, nullptr,
              SEQ, INTER, HIDDEN, 1|2);
        gemma(ph16, pf2w16+(long)i*HIDDEN*INTER, px, fc2_b+(long)i*HIDDEN, px,
              SEQ, HIDDEN, INTER, 0);

        if(i==2 || i==4){
            int j = (i==2) ? 0 : 1;
            __half* dh = pdh16 + (long)j*1024*MERGED;
            __half* df = pdf16 + (long)j*1024*MERGED;
            // LN reads px on the MAIN stream (px is rewritten by the next layer)
            ln_kernel<<<1024,256>>>(px, ds_ln_g+(long)j*MERGED, ds_ln_b+(long)j*MERGED, dh, MERGED);
            // fork: the two big merger GEMMs run on the side stream
            cudaEvent_t fk = (j==0) ? s_fork0 : s_fork1;
            cudaEventRecord(fk, 0);
            cudaStreamWaitEvent(s_side, fk, 0);
            gemma_s(s_side, dh, pd1w16+(long)j*MERGED*MERGED, df, ds_fc1_b+(long)j*MERGED, nullptr,
                    1024, MERGED, MERGED, 1|2);
            gemma_s(s_side, df, pd2w16+(long)j*OUTH*MERGED, out+(long)(1+j)*1024*OUTH,
                    ds_fc2_b+(long)j*OUTH, nullptr,
                    1024, OUTH, MERGED, 0);
            if(j==1) cudaEventRecord(s_join, s_side);
        }
    }

    ln_kernel<<<SEQ,256>>>(px, m_ln_g, m_ln_b, pmh16, HIDDEN);
    gemma(pmh16, pm1w16, pmf16, m_fc1_b, nullptr, 1024, MERGED, MERGED, 1|2);
    gemma(pmf16, pm2w16, out, m_fc2_b, nullptr, 1024, OUTH, MERGED, 0);

    // join side stream into main before returning
    cudaStreamWaitEvent(0, s_join, 0);
}

// round 16
// speedup vs baseline: 1.0713x; 1.0099x over previous
#include <cuda_runtime.h>
#include <cuda_fp16.h>
#include <math.h>
#include <stdint.h>

// ---------------- problem constants ----------------
#define SEQ      4096
#define HIDDEN   1152
#define HEADS    16
#define HD       72
#define INTER    4304
#define DEPTH    6
#define MERGED   4608
#define OUTH     2048
#define PATCHD   1536
#define IMG_TOK  1024
#define NBH      64
#define SCALE_Q  0.11785113019775793f

// ---------------- device scratch ----------------
__device__ __half w16_patch[HIDDEN*PATCHD];
__device__ __half w16_qkv [DEPTH*3*HIDDEN*HIDDEN];
__device__ __half w16_proj[DEPTH*HIDDEN*HIDDEN];
__device__ __half w16_fc1 [DEPTH*INTER*HIDDEN];
__device__ __half w16_fc2 [DEPTH*HIDDEN*INTER];
__device__ __half w16_mfc1[MERGED*MERGED];
__device__ __half w16_mfc2[OUTH*MERGED];
__device__ __half w16_dfc1[2*MERGED*MERGED];
__device__ __half w16_dfc2[2*OUTH*MERGED];
__device__ __half g_px16  [SEQ*PATCHD];
__device__ __half g_xn16  [SEQ*HIDDEN];
__device__ __half g_qkv16 [SEQ*3*HIDDEN];
__device__ __half g_q16   [NBH*IMG_TOK*HD];
__device__ __half g_k16   [NBH*IMG_TOK*HD];
__device__ __half g_v16t  [NBH*HD*IMG_TOK];
__device__ __half g_at16  [SEQ*HIDDEN];
__device__ __half g_h16   [SEQ*INTER];
__device__ __half g_mh16  [SEQ*HIDDEN];
__device__ __half g_mf16  [1024*MERGED];
__device__ __half g_dh16  [2][1024*MERGED];
__device__ __half g_df16  [2][1024*MERGED];
__device__ float g_x   [SEQ*HIDDEN];
__device__ float g_cos [IMG_TOK*HD];
__device__ float g_sin [IMG_TOK*HD];

// ---------------- helpers ----------------
__device__ __forceinline__ float gelu_f(float x){
    float x3 = x*x*x;
    return 0.5f*x*(1.0f + tanhf(0.7978845608028654f*(x + 0.044715f*x3)));
}
__device__ __forceinline__ uint32_t h2u(float a, float b){
    __half2 h = __floats2half2_rn(a, b);
    return *(uint32_t*)&h;
}
__device__ __forceinline__ void mma16(float* c, const uint32_t* a, const uint32_t* b){
    asm volatile("mma.sync.aligned.m16n8k16.row.col.f32.f16.f16.f32 "
        "{%0,%1,%2,%3},{%4,%5,%6,%7},{%8,%9},{%0,%1,%2,%3};"
        : "+f"(c[0]),"+f"(c[1]),"+f"(c[2]),"+f"(c[3])
        : "r"(a[0]),"r"(a[1]),"r"(a[2]),"r"(a[3]),"r"(b[0]),"r"(b[1]));
}
#define LDSM4(r, addr) \
    asm volatile("ldmatrix.sync.aligned.m8n8.x4.shared.b16 {%0,%1,%2,%3}, [%4];" \
        : "=r"((r)[0]),"=r"((r)[1]),"=r"((r)[2]),"=r"((r)[3]) : "r"(addr))
__device__ __forceinline__ void cp16(void* dst, const void* src, int nbytes){
    asm volatile("cp.async.cg.shared.global [%0], [%1], 16, %2;"
        :: "r"((uint32_t)__cvta_generic_to_shared(dst)), "l"(src), "r"(nbytes) : "memory");
}
#define CP_COMMIT() asm volatile("cp.async.commit_group;" ::: "memory")
#define CP_WAIT1()  asm volatile("cp.async.wait_group 1;" ::: "memory")
#define CP_WAIT0()  asm volatile("cp.async.wait_group 0;" ::: "memory")

__device__ __forceinline__ float blockReduceSum(float v, float* sh){
    int tid = threadIdx.x;
    __syncthreads();
    #pragma unroll
    for(int o=16;o>0;o>>=1) v += __shfl_xor_sync(0xffffffffu, v, o);
    if((tid&31)==0) sh[tid>>5] = v;
    __syncthreads();
    if(tid < 32){
        float r = (tid < (int)(blockDim.x>>5)) ? sh[tid] : 0.f;
        #pragma unroll
        for(int o=16;o>0;o>>=1) r += __shfl_xor_sync(0xffffffffu, r, o);
        if(tid==0) sh[0] = r;
    }
    __syncthreads();
    return sh[0];
}

// ---------------- vectorized fp32 -> fp16 ----------------
__global__ void f2h(const float4* __restrict__ s, __half2* __restrict__ d, long n4){
    long i = (long)blockIdx.x*blockDim.x + threadIdx.x;
    long stride = (long)gridDim.x*blockDim.x;
    for(; i<n4; i+=stride){
        float4 v = s[i];
        d[2*i  ] = __floats2half2_rn(v.x, v.y);
        d[2*i+1] = __floats2half2_rn(v.z, v.w);
    }
}

// ---------------- fp16 GEMM: 128x128, K-chunk 64, 3-stage, 1 barrier/iter ----------------
#define GST 72
#define A_ST  (128*GST)
#define GSMEM (6*A_ST*2)       // 110592 bytes

__global__ __launch_bounds__(256,2)
void gemm_a(const __half* __restrict__ A, const __half* __restrict__ B,
            void* __restrict__ Cv, const float* __restrict__ bias,
            const float* __restrict__ res,
            int M, int N, int K, int flags)
{
    extern __shared__ __half smh[];
    __half* As = smh;
    __half* Bs = smh + 3*A_ST;

    const int tid  = threadIdx.x;
    const int lane = tid & 31, warp = tid >> 5;
    const int g = lane >> 2, tq = lane & 3;
    const int wm = warp >> 1, wn = warp & 1;
    const int m0 = wm*32, n0 = wn*64;
    const int bn = blockIdx.x, bm = blockIdx.y;

    float acc[2][8][4];
    #pragma unroll
    for(int i=0;i<2;i++)
        #pragma unroll
        for(int j=0;j<8;j++)
            #pragma unroll
            for(int q=0;q<4;q++) acc[i][j][q]=0.f;

    const int NT = (K+63)/64;
    const int lr  = tid >> 3;
    const int seg = tid & 7;

    auto loadStage = [&](int st, int k0){
        int kh  = k0 + seg*8;
        int nb  = (K - kh)*2; nb = nb < 0 ? 0 : (nb > 16 ? 16 : nb);
        int khc = kh < K ? kh : 0;
        #pragma unroll
        for(int i=0;i<4;i++){
            int row = lr + i*32;
            cp16(As + st*A_ST + row*GST + seg*8,
                 A + (long)(bm*128+row)*K + khc, nb);
            int brow = bn*128 + row;
            cp16(Bs + st*A_ST + row*GST + seg*8,
                 B + (long)(brow < N ? brow : 0)*K + khc, brow < N ? nb : 0);
        }
    };

    loadStage(0, 0); CP_COMMIT();
    if(NT > 1){ loadStage(1, 64); CP_COMMIT(); }

    for(int kt=0; kt<NT; kt++){
        if(kt+1 < NT){ CP_WAIT1(); } else { CP_WAIT0(); }
        __syncthreads();

        const int st = kt % 3;
        const uint32_t abase = (uint32_t)__cvta_generic_to_shared(As + st*A_ST);
        const uint32_t bbase = (uint32_t)__cvta_generic_to_shared(Bs + st*A_ST);
        const int lrow = lane & 15, lcol = (lane >> 4) * 8;
        #pragma unroll
        for(int s=0;s<4;s++){
            uint32_t af[2][4];
            #pragma unroll
            for(int mt=0;mt<2;mt++){
                uint32_t ad = abase + ((m0 + mt*16 + lrow)*GST + s*16 + lcol)*2;
                LDSM4(af[mt], ad);
            }
            uint32_t bq[4][4];
            #pragma unroll
            for(int p=0;p<4;p++){
                uint32_t bd = bbase + ((n0 + p*16 + lrow)*GST + s*16 + lcol)*2;
                LDSM4(bq[p], bd);
            }
            #pragma unroll
            for(int mt=0;mt<2;mt++)
                #pragma unroll
                for(int nt=0;nt<8;nt++){
                    uint32_t bf[2] = { bq[nt>>1][nt&1], bq[nt>>1][2+(nt&1)] };
                    mma16(acc[mt][nt], af[mt], bf);
                }
        }
        if(kt+2 < NT){ loadStage((kt+2)%3, (kt+2)*64); CP_COMMIT(); }
    }

    const int dogelu = flags & 1, out16 = flags & 2;
    float* Cf = (float*)Cv;
    __half* Ch = (__half*)Cv;
    #pragma unroll
    for(int mt=0;mt<2;mt++){
        int r0 = bm*128 + m0 + mt*16 + g;
        int r1 = r0 + 8;
        #pragma unroll
        for(int nt=0;nt<8;nt++){
            int col = bn*128 + n0 + nt*8 + tq*2;
            if(col < N){
                float v0 = acc[mt][nt][0], v1 = acc[mt][nt][1];
                float v2 = acc[mt][nt][2], v3 = acc[mt][nt][3];
                if(bias){ float b0=bias[col], b1=bias[col+1]; v0+=b0; v1+=b1; v2+=b0; v3+=b1; }
                if(dogelu){ v0=gelu_f(v0); v1=gelu_f(v1); v2=gelu_f(v2); v3=gelu_f(v3); }
                long i0 = (long)r0*N + col, i1 = (long)r1*N + col;
                if(out16){
                    *(__half2*)(Ch + i0) = __floats2half2_rn(v0, v1);
                    *(__half2*)(Ch + i1) = __floats2half2_rn(v2, v3);
                } else {
                    if(res){ v0+=res[i0]; v1+=res[i0+1]; v2+=res[i1]; v3+=res[i1+1]; }
                    Cf[i0]=v0; Cf[i0+1]=v1; Cf[i1]=v2; Cf[i1+1]=v3;
                }
            }
        }
    }
}

// ---------------- fused flash attention: 3-stage cp.async K/V pipeline ----------------
#define QST 44
#define VST 36
#define K_ST (64*QST)
#define V_ST (72*VST)
#define FSMEM ((128*QST + 3*K_ST + 3*V_ST)*4)   // 87424 bytes

__global__ __launch_bounds__(256,2)
void flash_attn(const __half* __restrict__ q2, const __half* __restrict__ k2,
                const __half* __restrict__ v2t, __half* __restrict__ attn)
{
    extern __shared__ uint32_t fsm[];
    uint32_t* Qs = fsm;
    uint32_t* Ks = fsm + 128*QST;
    uint32_t* Vs = Ks + 3*K_ST;

    const int tid = threadIdx.x;
    const int lane = tid & 31, w = tid >> 5;
    const int g = lane >> 2, tq = lane & 3;
    const int qb = blockIdx.x, bh = blockIdx.y;

    const __half* Kg0 = k2  + (long)bh*IMG_TOK*HD;
    const __half* Vg0 = v2t + (long)bh*HD*IMG_TOK;

    auto loadKV = [&](int st, int kb){
        const __half* Kg = Kg0 + (long)kb*64*HD;
        for(int idx = tid; idx < 576; idx += 256){
            int r = idx/9, c = idx%9;
            cp16(Ks + st*K_ST + r*QST + c*4, Kg + (long)r*HD + c*8, 16);
        }
        const __half* Vg = Vg0 + kb*64;
        for(int idx = tid; idx < 576; idx += 256){
            int r = idx/8, c = idx%8;
            cp16(Vs + st*V_ST + r*VST + c*4, Vg + (long)r*IMG_TOK + c*8, 16);
        }
    };

    for(int idx = tid; idx < 3*64*4; idx += 256){
        int st = idx/256, rem = idx%256, r = rem>>2, c = rem&3;
        Ks[st*K_ST + r*QST + 36 + c] = 0;
    }
    const __half* Qg = q2 + ((long)bh*IMG_TOK + qb*128)*HD;
    for(int idx = tid; idx < 128*40; idx += 256){
        int r = idx/40, c = idx%40;
        Qs[r*QST + c] = (c < 36) ? *(const uint32_t*)(Qg + (long)r*HD + 2*c) : 0u;
    }

    loadKV(0, 0); CP_COMMIT();
    loadKV(1, 1); CP_COMMIT();
    __syncthreads();

    uint32_t qf[5][4];
    #pragma unroll
    for(int s=0;s<5;s++){
        qf[s][0] = Qs[(w*16+g  )*QST + s*8 + tq    ];
        qf[s][1] = Qs[(w*16+8+g)*QST + s*8 + tq    ];
        qf[s][2] = Qs[(w*16+g  )*QST + s*8 + tq + 4];
        qf[s][3] = Qs[(w*16+8+g)*QST + s*8 + tq + 4];
    }

    float m0 = -3.4e38f, m1 = -3.4e38f, l0 = 0.f, l1 = 0.f;
    float o[9][4];
    #pragma unroll
    for(int nt=0;nt<9;nt++){ o[nt][0]=0.f; o[nt][1]=0.f; o[nt][2]=0.f; o[nt][3]=0.f; }

    for(int kb=0; kb<16; kb++){
        if(kb+1 < 16){ CP_WAIT1(); } else { CP_WAIT0(); }
        __syncthreads();

        const uint32_t* Kst = Ks + (kb%3)*K_ST;
        const uint32_t* Vst = Vs + (kb%3)*V_ST;

        float sacc[8][4];
        #pragma unroll
        for(int nt=0;nt<8;nt++){ sacc[nt][0]=0.f; sacc[nt][1]=0.f; sacc[nt][2]=0.f; sacc[nt][3]=0.f; }
        #pragma unroll
        for(int s=0;s<5;s++){
            #pragma unroll
            for(int nt=0;nt<8;nt++){
                uint32_t bf[2];
                bf[0] = Kst[(nt*8+g)*QST + s*8 + tq    ];
                bf[1] = Kst[(nt*8+g)*QST + s*8 + tq + 4];
                mma16(sacc[nt], qf[s], bf);
            }
        }

        float rm0 = -3.4e38f, rm1 = -3.4e38f;
        #pragma unroll
        for(int nt=0;nt<8;nt++){
            rm0 = fmaxf(rm0, fmaxf(sacc[nt][0], sacc[nt][1]));
            rm1 = fmaxf(rm1, fmaxf(sacc[nt][2], sacc[nt][3]));
        }
        rm0 = fmaxf(rm0, __shfl_xor_sync(0xffffffffu, rm0, 1));
        rm0 = fmaxf(rm0, __shfl_xor_sync(0xffffffffu, rm0, 2));
        rm1 = fmaxf(rm1, __shfl_xor_sync(0xffffffffu, rm1, 1));
        rm1 = fmaxf(rm1, __shfl_xor_sync(0xffffffffu, rm1, 2));

        float m0n = fmaxf(m0, rm0), m1n = fmaxf(m1, rm1);
        float a0 = __expf(m0 - m0n), a1 = __expf(m1 - m1n);
        m0 = m0n; m1 = m1n;

        float rs0 = 0.f, rs1 = 0.f;
        #pragma unroll
        for(int nt=0;nt<8;nt++){
            sacc[nt][0] = __expf(sacc[nt][0] - m0n);
            sacc[nt][1] = __expf(sacc[nt][1] - m0n);
            sacc[nt][2] = __expf(sacc[nt][2] - m1n);
            sacc[nt][3] = __expf(sacc[nt][3] - m1n);
            rs0 += sacc[nt][0] + sacc[nt][1];
            rs1 += sacc[nt][2] + sacc[nt][3];
        }
        rs0 += __shfl_xor_sync(0xffffffffu, rs0, 1);
        rs0 += __shfl_xor_sync(0xffffffffu, rs0, 2);
        rs1 += __shfl_xor_sync(0xffffffffu, rs1, 1);
        rs1 += __shfl_xor_sync(0xffffffffu, rs1, 2);
        l0 = l0*a0 + rs0;
        l1 = l1*a1 + rs1;

        #pragma unroll
        for(int nt=0;nt<9;nt++){
            o[nt][0]*=a0; o[nt][1]*=a0; o[nt][2]*=a1; o[nt][3]*=a1;
        }

        #pragma unroll
        for(int ks=0;ks<4;ks++){
            uint32_t pf[4];
            pf[0] = h2u(sacc[2*ks  ][0], sacc[2*ks  ][1]);
            pf[1] = h2u(sacc[2*ks  ][2], sacc[2*ks  ][3]);
            pf[2] = h2u(sacc[2*ks+1][0], sacc[2*ks+1][1]);
            pf[3] = h2u(sacc[2*ks+1][2], sacc[2*ks+1][3]);
            #pragma unroll
            for(int nt=0;nt<9;nt++){
                uint32_t bf[2];
                bf[0] = Vst[(nt*8+g)*VST + ks*8 + tq    ];
                bf[1] = Vst[(nt*8+g)*VST + ks*8 + tq + 4];
                mma16(o[nt], pf, bf);
            }
        }

        if(kb+2 < 16){ loadKV((kb+2)%3, kb+2); CP_COMMIT(); }
    }

    float inv0 = 1.f/l0, inv1 = 1.f/l1;
    int b = bh >> 4, h = bh & 15;
    int t0 = qb*128 + w*16 + g;
    long base0 = (long)(b*IMG_TOK + t0    )*HIDDEN + h*HD;
    long base1 = (long)(b*IMG_TOK + t0 + 8)*HIDDEN + h*HD;
    #pragma unroll
    for(int nt=0;nt<9;nt++){
        int col = nt*8 + tq*2;
        *(__half2*)(attn + base0 + col) = __floats2half2_rn(o[nt][0]*inv0, o[nt][1]*inv0);
        *(__half2*)(attn + base1 + col) = __floats2half2_rn(o[nt][2]*inv1, o[nt][3]*inv1);
    }
}

// ---------------- LayerNorm (fp32 in, fp16 out; vectorized) ----------------
__global__ void ln_kernel(const float* __restrict__ x, const float* __restrict__ g,
                          const float* __restrict__ b, __half* __restrict__ y, int N)
{
    __shared__ float sh[32];
    const int n4 = N >> 2;
    const float4* X4 = (const float4*)(x + (long)blockIdx.x * N);
    const float4* G4 = (const float4*)g;
    const float4* B4 = (const float4*)b;
    __half2* Y2 = (__half2*)(y + (long)blockIdx.x * N);

    float s=0.f, ss=0.f;
    for(int c=threadIdx.x;c<n4;c+=blockDim.x){
        float4 v = X4[c];
        s  += v.x + v.y + v.z + v.w;
        ss += v.x*v.x + v.y*v.y + v.z*v.z + v.w*v.w;
    }
    s  = blockReduceSum(s,  sh);
    ss = blockReduceSum(ss, sh);
    float mu  = s  / (float)N;
    float var = ss / (float)N - mu*mu;
    float rs  = rsqrtf(var + 1e-6f);
    for(int c=threadIdx.x;c<n4;c+=blockDim.x){
        float4 v = X4[c];
        float4 gg = G4[c], bb = B4[c];
        Y2[2*c  ] = __floats2half2_rn((v.x-mu)*rs*gg.x + bb.x, (v.y-mu)*rs*gg.y + bb.y);
        Y2[2*c+1] = __floats2half2_rn((v.z-mu)*rs*gg.z + bb.z, (v.w-mu)*rs*gg.w + bb.w);
    }
}

// ---------------- RoPE tables ----------------
__global__ void init_rope()
{
    int gid = blockIdx.x*blockDim.x + threadIdx.x;
    if(gid >= IMG_TOK*HD) return;
    int d = gid % HD, tt = gid / HD;
    int iw=tt&1, ih=(tt>>1)&1, bw=(tt>>2)&15, bh=tt>>6;
    int gh = bh*2+ih, gw = bw*2+iw;
    int dd = d % 36;
    int pos, i;
    if(dd < 18){ i = dd;      pos = gh; }
    else       { i = dd - 18; pos = gw; }
    float inv = powf(10000.0f, -((float)(2*i)/36.0f));
    float ang = (float)pos * inv;
    g_cos[gid] = cosf(ang);
    g_sin[gid] = sinf(ang);
}

// ---------------- pos-embed bilinear add ----------------
__global__ void add_pos(float* __restrict__ x, const float* __restrict__ pe)
{
    int gid = blockIdx.x*blockDim.x + threadIdx.x;
    if(gid >= SEQ*HIDDEN) return;
    int j = gid % HIDDEN; int s = gid / HIDDEN;
    int tt = s & 1023;
    int iw=tt&1, ih=(tt>>1)&1, bw=(tt>>2)&15, bh=tt>>6;
    int gh = bh*2+ih, gw = bw*2+iw;
    double hl = (double)gh*47.0/31.0;
    double wl = (double)gw*47.0/31.0;
    int h0=(int)hl; int h1=min(h0+1,47); float dh=(float)(hl-(double)h0);
    int w0=(int)wl; int w1=min(w0+1,47); float dw=(float)(wl-(double)w0);
    float p00 = pe[(h0*48+w0)*HIDDEN + j];
    float p01 = pe[(h0*48+w1)*HIDDEN + j];
    float p10 = pe[(h1*48+w0)*HIDDEN + j];
    float p11 = pe[(h1*48+w1)*HIDDEN + j];
    float v = (1.f-dh)*((1.f-dw)*p00 + dw*p01) + dh*((1.f-dw)*p10 + dw*p11);
    x[gid] += v;
}

// ---------------- fused RoPE(Q,K) + V transpose ----------------
__global__ void rope_pack2(const __half* __restrict__ qkv, __half* __restrict__ q2,
                           __half* __restrict__ k2, __half* __restrict__ v16t)
{
    __shared__ __half tile[64][80];
    const int tb = blockIdx.x, bh = blockIdx.y;
    const int b = bh >> 4, h = bh & 15;
    const int tid = threadIdx.x;

    for(int idx = tid; idx < 64*HD; idx += 256){
        int r = idx / HD, d = idx % HD;
        int tt = tb*64 + r;
        long base = (long)(b*IMG_TOK + tt)*(3*HIDDEN) + h*HD;
        float c  = g_cos[tt*HD + d];
        float sn = g_sin[tt*HD + d];
        float qd = __half2float(qkv[base + d]);
        float kd = __half2float(qkv[base + HIDDEN + d]);
        int   dp  = (d<36) ? d+36 : d-36;
        float sgn = (d<36) ? -1.f : 1.f;
        float qp = __half2float(qkv[base + dp]);
        float kp = __half2float(qkv[base + HIDDEN + dp]);
        long oi = ((long)bh*IMG_TOK + tt)*HD + d;
        q2[oi] = __float2half((qd*c + sgn*qp*sn) * SCALE_Q);
        k2[oi] = __float2half( kd*c + sgn*kp*sn);
        tile[r][d] = qkv[base + 2*HIDDEN + d];
    }
    __syncthreads();
    for(int idx = tid; idx < HD*64; idx += 256){
        int rr = idx / 64, cc = idx % 64;
        v16t[((long)bh*HD + rr)*IMG_TOK + tb*64 + cc] = tile[cc][rr];
    }
}

// ---------------- host helpers ----------------
static inline void gemma_s(cudaStream_t st, const __half*A,const __half*B,void*C,
                           const float*bias,const float*res,
                           int M,int N,int K,int flags){
    dim3 g((N+127)/128, M/128);
    gemm_a<<<g,256,GSMEM,st>>>(A,B,C,bias,res,M,N,K,flags);
}
static inline void gemma(const __half*A,const __half*B,void*C,const float*bias,const float*res,
                         int M,int N,int K,int flags){
    gemma_s(0, A,B,C,bias,res,M,N,K,flags);
}

extern "C" void kernel_launch(void* const* d_in, const int* in_sizes, int n_in,
                              void* d_out, int out_size)
{
    const float* pixel   = (const float*)d_in[0];
    const float* patch_w = (const float*)d_in[1];
    const float* patch_b = (const float*)d_in[2];
    const float* pos_e   = (const float*)d_in[3];
    const float* qkv_w   = (const float*)d_in[4];
    const float* qkv_b   = (const float*)d_in[5];
    const float* proj_w  = (const float*)d_in[6];
    const float* proj_b  = (const float*)d_in[7];
    const float* ln1_g   = (const float*)d_in[8];
    const float* ln1_b   = (const float*)d_in[9];
    const float* ln2_g   = (const float*)d_in[10];
    const float* ln2_b   = (const float*)d_in[11];
    const float* fc1_w   = (const float*)d_in[12];
    const float* fc1_b   = (const float*)d_in[13];
    const float* fc2_w   = (const float*)d_in[14];
    const float* fc2_b   = (const float*)d_in[15];
    const float* m_ln_g  = (const float*)d_in[16];
    const float* m_ln_b  = (const float*)d_in[17];
    const float* m_fc1_w = (const float*)d_in[18];
    const float* m_fc1_b = (const float*)d_in[19];
    const float* m_fc2_w = (const float*)d_in[20];
    const float* m_fc2_b = (const float*)d_in[21];
    const float* ds_ln_g = (const float*)d_in[22];
    const float* ds_ln_b = (const float*)d_in[23];
    const float* ds_fc1_w= (const float*)d_in[24];
    const float* ds_fc1_b= (const float*)d_in[25];
    const float* ds_fc2_w= (const float*)d_in[26];
    const float* ds_fc2_b= (const float*)d_in[27];
    float* out = (float*)d_out;

    cudaFuncSetAttribute(gemm_a, cudaFuncAttributeMaxDynamicSharedMemorySize, GSMEM);
    cudaFuncSetAttribute(flash_attn, cudaFuncAttributeMaxDynamicSharedMemorySize, FSMEM);

    static cudaStream_t s_side = [](){ cudaStream_t t; cudaStreamCreate(&t); return t; }();
    auto mkev = [](){ cudaEvent_t e; cudaEventCreateWithFlags(&e, cudaEventDisableTiming); return e; };
    static cudaEvent_t s_e0    = mkev();
    static cudaEvent_t s_eqkv  = mkev();
    static cudaEvent_t s_emlp  = mkev();
    static cudaEvent_t s_emrg  = mkev();
    static cudaEvent_t s_fork0 = mkev();
    static cudaEvent_t s_fork1 = mkev();
    static cudaEvent_t s_join  = mkev();

    float *px;
    __half *pw16,*pqw16,*ppw16,*pf1w16,*pf2w16,*pm1w16,*pm2w16,*pd1w16,*pd2w16,*ppx16;
    __half *pxn16,*pqkv16,*pq16,*pk16,*pv16t,*pat16,*ph16,*pmh16,*pmf16,*pdh16,*pdf16;
    cudaGetSymbolAddress((void**)&px,    g_x);
    cudaGetSymbolAddress((void**)&pw16,  w16_patch);
    cudaGetSymbolAddress((void**)&pqw16, w16_qkv);
    cudaGetSymbolAddress((void**)&ppw16, w16_proj);
    cudaGetSymbolAddress((void**)&pf1w16,w16_fc1);
    cudaGetSymbolAddress((void**)&pf2w16,w16_fc2);
    cudaGetSymbolAddress((void**)&pm1w16,w16_mfc1);
    cudaGetSymbolAddress((void**)&pm2w16,w16_mfc2);
    cudaGetSymbolAddress((void**)&pd1w16,w16_dfc1);
    cudaGetSymbolAddress((void**)&pd2w16,w16_dfc2);
    cudaGetSymbolAddress((void**)&ppx16, g_px16);
    cudaGetSymbolAddress((void**)&pxn16, g_xn16);
    cudaGetSymbolAddress((void**)&pqkv16,g_qkv16);
    cudaGetSymbolAddress((void**)&pq16,  g_q16);
    cudaGetSymbolAddress((void**)&pk16,  g_k16);
    cudaGetSymbolAddress((void**)&pv16t, g_v16t);
    cudaGetSymbolAddress((void**)&pat16, g_at16);
    cudaGetSymbolAddress((void**)&ph16,  g_h16);
    cudaGetSymbolAddress((void**)&pmh16, g_mh16);
    cudaGetSymbolAddress((void**)&pmf16, g_mf16);
    cudaGetSymbolAddress((void**)&pdh16, g_dh16);
    cudaGetSymbolAddress((void**)&pdf16, g_df16);

    const int EW = 256;

    auto F2Hs = [&](cudaStream_t st, const float* s, __half* d, long n){
        long n4 = n/4;
        int grid = (int)((n4 + 255)/256); if(grid > 4096) grid = 4096;
        f2h<<<grid, 256, 0, st>>>((const float4*)s, (__half2*)d, n4);
    };

    // fork side stream at entry
    cudaEventRecord(s_e0, 0);
    cudaStreamWaitEvent(s_side, s_e0, 0);

    // main: immediately-needed work
    init_rope<<<(IMG_TOK*HD + EW-1)/EW, EW>>>();
    F2Hs(0, pixel,   ppx16, (long)SEQ*PATCHD);
    F2Hs(0, patch_w, pw16,  (long)HIDDEN*PATCHD);

    // side: staged weight conversions
    F2Hs(s_side, qkv_w, pqw16, (long)DEPTH*3*HIDDEN*HIDDEN);
    cudaEventRecord(s_eqkv, s_side);
    F2Hs(s_side, proj_w, ppw16,  (long)DEPTH*HIDDEN*HIDDEN);
    F2Hs(s_side, fc1_w,  pf1w16, (long)DEPTH*INTER*HIDDEN);
    F2Hs(s_side, fc2_w,  pf2w16, (long)DEPTH*HIDDEN*INTER);
    cudaEventRecord(s_emlp, s_side);
    F2Hs(s_side, ds_fc1_w, pd1w16, (long)2*MERGED*MERGED);
    F2Hs(s_side, ds_fc2_w, pd2w16, (long)2*OUTH*MERGED);
    F2Hs(s_side, m_fc1_w,  pm1w16, (long)MERGED*MERGED);
    F2Hs(s_side, m_fc2_w,  pm2w16, (long)OUTH*MERGED);
    cudaEventRecord(s_emrg, s_side);

    gemma(ppx16, pw16, px, patch_b, nullptr, SEQ, HIDDEN, PATCHD, 0);
    add_pos<<<(SEQ*HIDDEN + EW-1)/EW, EW>>>(px, pos_e);

    for(int i=0;i<DEPTH;i++){
        ln_kernel<<<SEQ,256>>>(px, ln1_g+(long)i*HIDDEN, ln1_b+(long)i*HIDDEN, pxn16, HIDDEN);
        if(i==0) cudaStreamWaitEvent(0, s_eqkv, 0);
        gemma(pxn16, pqw16+(long)i*3*HIDDEN*HIDDEN, pqkv16, qkv_b+(long)i*3*HIDDEN, nullptr,
              SEQ, 3*HIDDEN, HIDDEN, 2);
        rope_pack2<<<dim3(16, NBH), 256>>>(pqkv16, pq16, pk16, pv16t);
        flash_attn<<<dim3(8, NBH), 256, FSMEM>>>(pq16, pk16, pv16t, pat16);
        if(i==0) cudaStreamWaitEvent(0, s_emlp, 0);
        gemma(pat16, ppw16+(long)i*HIDDEN*HIDDEN, px, proj_b+(long)i*HIDDEN, px,
              SEQ, HIDDEN, HIDDEN, 0);

        ln_kernel<<<SEQ,256>>>(px, ln2_g+(long)i*HIDDEN, ln2_b+(long)i*HIDDEN, pxn16, HIDDEN);
        gemma(pxn16, pf1w16+(long)i*INTER*HIDDEN, ph16, fc1_b+(long)i*INTER, nullptr,
              SEQ, INTER, HIDDEN, 1|2);
        gemma(ph16, pf2w16+(long)i*HIDDEN*INTER, px, fc2_b+(long)i*HIDDEN, px,
              SEQ, HIDDEN, INTER, 0);

        if(i==2 || i==4){
            int j = (i==2) ? 0 : 1;
            __half* dh = pdh16 + (long)j*1024*MERGED;
            __half* df = pdf16 + (long)j*1024*MERGED;
            // LN reads px on the MAIN stream
            ln_kernel<<<1024,256>>>(px, ds_ln_g+(long)j*MERGED, ds_ln_b+(long)j*MERGED, dh, MERGED);
            cudaEvent_t fk = (j==0) ? s_fork0 : s_fork1;
            cudaEventRecord(fk, 0);
            cudaStreamWaitEvent(s_side, fk, 0);
            // side stream: merger weights already converted on this stream (ordered)
            gemma_s(s_side, dh, pd1w16+(long)j*MERGED*MERGED, df, ds_fc1_b+(long)j*MERGED, nullptr,
                    1024, MERGED, MERGED, 1|2);
            gemma_s(s_side, df, pd2w16+(long)j*OUTH*MERGED, out+(long)(1+j)*1024*OUTH,
                    ds_fc2_b+(long)j*OUTH, nullptr,
                    1024, OUTH, MERGED, 0);
            if(j==1) cudaEventRecord(s_join, s_side);
        }
    }

    ln_kernel<<<SEQ,256>>>(px, m_ln_g, m_ln_b, pmh16, HIDDEN);
    cudaStreamWaitEvent(0, s_emrg, 0);
    gemma(pmh16, pm1w16, pmf16, m_fc1_b, nullptr, 1024, MERGED, MERGED, 1|2);
    gemma(pmf16, pm2w16, out, m_fc2_b, nullptr, 1024, OUTH, MERGED, 0);

    cudaStreamWaitEvent(0, s_join, 0);
}

// round 17
// speedup vs baseline: 1.1238x; 1.0490x over previous
#include <cuda_runtime.h>
#include <cuda_fp16.h>
#include <math.h>
#include <stdint.h>

// ---------------- problem constants ----------------
#define SEQ      4096
#define HIDDEN   1152
#define HEADS    16
#define HD       72
#define INTER    4304
#define DEPTH    6
#define MERGED   4608
#define OUTH     2048
#define PATCHD   1536
#define IMG_TOK  1024
#define NBH      64
#define SCALE_Q  0.11785113019775793f

// ---------------- device scratch ----------------
__device__ __half w16_patch[HIDDEN*PATCHD];
__device__ __half w16_qkv [DEPTH*3*HIDDEN*HIDDEN];
__device__ __half w16_proj[DEPTH*HIDDEN*HIDDEN];
__device__ __half w16_fc1 [DEPTH*INTER*HIDDEN];
__device__ __half w16_fc2 [DEPTH*HIDDEN*INTER];
__device__ __half w16_mfc1[MERGED*MERGED];
__device__ __half w16_mfc2[OUTH*MERGED];
__device__ __half w16_dfc1[2*MERGED*MERGED];
__device__ __half w16_dfc2[2*OUTH*MERGED];
__device__ __half g_px16  [SEQ*PATCHD];
__device__ __half g_xn16  [SEQ*HIDDEN];
__device__ __half g_qkv16 [SEQ*3*HIDDEN];
__device__ __half g_q16   [NBH*IMG_TOK*HD];
__device__ __half g_k16   [NBH*IMG_TOK*HD];
__device__ __half g_v16t  [NBH*HD*IMG_TOK];
__device__ __half g_at16  [SEQ*HIDDEN];
__device__ __half g_h16   [SEQ*INTER];
__device__ __half g_mh16  [SEQ*HIDDEN];
__device__ __half g_mf16  [1024*MERGED];
__device__ __half g_dh16  [2][1024*MERGED];
__device__ __half g_df16  [2][1024*MERGED];
__device__ float g_x   [SEQ*HIDDEN];
__device__ float g_pe  [IMG_TOK*HIDDEN];
__device__ float g_cos [IMG_TOK*HD];
__device__ float g_sin [IMG_TOK*HD];

// ---------------- helpers ----------------
__device__ __forceinline__ float gelu_f(float x){
    float x3 = x*x*x;
    return 0.5f*x*(1.0f + tanhf(0.7978845608028654f*(x + 0.044715f*x3)));
}
__device__ __forceinline__ uint32_t h2u(float a, float b){
    __half2 h = __floats2half2_rn(a, b);
    return *(uint32_t*)&h;
}
__device__ __forceinline__ void mma16(float* c, const uint32_t* a, const uint32_t* b){
    asm volatile("mma.sync.aligned.m16n8k16.row.col.f32.f16.f16.f32 "
        "{%0,%1,%2,%3},{%4,%5,%6,%7},{%8,%9},{%0,%1,%2,%3};"
        : "+f"(c[0]),"+f"(c[1]),"+f"(c[2]),"+f"(c[3])
        : "r"(a[0]),"r"(a[1]),"r"(a[2]),"r"(a[3]),"r"(b[0]),"r"(b[1]));
}
#define LDSM4(r, addr) \
    asm volatile("ldmatrix.sync.aligned.m8n8.x4.shared.b16 {%0,%1,%2,%3}, [%4];" \
        : "=r"((r)[0]),"=r"((r)[1]),"=r"((r)[2]),"=r"((r)[3]) : "r"(addr))
__device__ __forceinline__ void cp16(void* dst, const void* src, int nbytes){
    asm volatile("cp.async.cg.shared.global [%0], [%1], 16, %2;"
        :: "r"((uint32_t)__cvta_generic_to_shared(dst)), "l"(src), "r"(nbytes) : "memory");
}
#define CP_COMMIT() asm volatile("cp.async.commit_group;" ::: "memory")
#define CP_WAIT1()  asm volatile("cp.async.wait_group 1;" ::: "memory")
#define CP_WAIT0()  asm volatile("cp.async.wait_group 0;" ::: "memory")

__device__ __forceinline__ float blockReduceSum(float v, float* sh){
    int tid = threadIdx.x;
    __syncthreads();
    #pragma unroll
    for(int o=16;o>0;o>>=1) v += __shfl_xor_sync(0xffffffffu, v, o);
    if((tid&31)==0) sh[tid>>5] = v;
    __syncthreads();
    if(tid < 32){
        float r = (tid < (int)(blockDim.x>>5)) ? sh[tid] : 0.f;
        #pragma unroll
        for(int o=16;o>0;o>>=1) r += __shfl_xor_sync(0xffffffffu, r, o);
        if(tid==0) sh[0] = r;
    }
    __syncthreads();
    return sh[0];
}

// ---------------- vectorized fp32 -> fp16 ----------------
__global__ void f2h(const float4* __restrict__ s, __half2* __restrict__ d, long n4){
    long i = (long)blockIdx.x*blockDim.x + threadIdx.x;
    long stride = (long)gridDim.x*blockDim.x;
    for(; i<n4; i+=stride){
        float4 v = s[i];
        d[2*i  ] = __floats2half2_rn(v.x, v.y);
        d[2*i+1] = __floats2half2_rn(v.z, v.w);
    }
}

// ---------------- fp16 GEMM: 128x128, K-chunk 64, 3-stage, 1 barrier/iter ----------------
// flags: 1=gelu, 2=out fp16, 4=res row wraps at 1024
#define GST 72
#define A_ST  (128*GST)
#define GSMEM (6*A_ST*2)       // 110592 bytes

__global__ __launch_bounds__(256,2)
void gemm_a(const __half* __restrict__ A, const __half* __restrict__ B,
            void* __restrict__ Cv, const float* __restrict__ bias,
            const float* __restrict__ res,
            int M, int N, int K, int flags)
{
    extern __shared__ __half smh[];
    __half* As = smh;
    __half* Bs = smh + 3*A_ST;

    const int tid  = threadIdx.x;
    const int lane = tid & 31, warp = tid >> 5;
    const int g = lane >> 2, tq = lane & 3;
    const int wm = warp >> 1, wn = warp & 1;
    const int m0 = wm*32, n0 = wn*64;
    const int bn = blockIdx.x, bm = blockIdx.y;

    float acc[2][8][4];
    #pragma unroll
    for(int i=0;i<2;i++)
        #pragma unroll
        for(int j=0;j<8;j++)
            #pragma unroll
            for(int q=0;q<4;q++) acc[i][j][q]=0.f;

    const int NT = (K+63)/64;
    const int lr  = tid >> 3;
    const int seg = tid & 7;

    auto loadStage = [&](int st, int k0){
        int kh  = k0 + seg*8;
        int nb  = (K - kh)*2; nb = nb < 0 ? 0 : (nb > 16 ? 16 : nb);
        int khc = kh < K ? kh : 0;
        #pragma unroll
        for(int i=0;i<4;i++){
            int row = lr + i*32;
            cp16(As + st*A_ST + row*GST + seg*8,
                 A + (long)(bm*128+row)*K + khc, nb);
            int brow = bn*128 + row;
            cp16(Bs + st*A_ST + row*GST + seg*8,
                 B + (long)(brow < N ? brow : 0)*K + khc, brow < N ? nb : 0);
        }
    };

    loadStage(0, 0); CP_COMMIT();
    if(NT > 1){ loadStage(1, 64); CP_COMMIT(); }

    for(int kt=0; kt<NT; kt++){
        if(kt+1 < NT){ CP_WAIT1(); } else { CP_WAIT0(); }
        __syncthreads();

        const int st = kt % 3;
        const uint32_t abase = (uint32_t)__cvta_generic_to_shared(As + st*A_ST);
        const uint32_t bbase = (uint32_t)__cvta_generic_to_shared(Bs + st*A_ST);
        const int lrow = lane & 15, lcol = (lane >> 4) * 8;
        #pragma unroll
        for(int s=0;s<4;s++){
            uint32_t af[2][4];
            #pragma unroll
            for(int mt=0;mt<2;mt++){
                uint32_t ad = abase + ((m0 + mt*16 + lrow)*GST + s*16 + lcol)*2;
                LDSM4(af[mt], ad);
            }
            uint32_t bq[4][4];
            #pragma unroll
            for(int p=0;p<4;p++){
                uint32_t bd = bbase + ((n0 + p*16 + lrow)*GST + s*16 + lcol)*2;
                LDSM4(bq[p], bd);
            }
            #pragma unroll
            for(int mt=0;mt<2;mt++)
                #pragma unroll
                for(int nt=0;nt<8;nt++){
                    uint32_t bf[2] = { bq[nt>>1][nt&1], bq[nt>>1][2+(nt&1)] };
                    mma16(acc[mt][nt], af[mt], bf);
                }
        }
        if(kt+2 < NT){ loadStage((kt+2)%3, (kt+2)*64); CP_COMMIT(); }
    }

    const int dogelu = flags & 1, out16 = flags & 2;
    const int rmask = (flags & 4) ? 1023 : 0x7fffffff;
    float* Cf = (float*)Cv;
    __half* Ch = (__half*)Cv;
    #pragma unroll
    for(int mt=0;mt<2;mt++){
        int r0 = bm*128 + m0 + mt*16 + g;
        int r1 = r0 + 8;
        #pragma unroll
        for(int nt=0;nt<8;nt++){
            int col = bn*128 + n0 + nt*8 + tq*2;
            if(col < N){
                float v0 = acc[mt][nt][0], v1 = acc[mt][nt][1];
                float v2 = acc[mt][nt][2], v3 = acc[mt][nt][3];
                if(bias){ float b0=bias[col], b1=bias[col+1]; v0+=b0; v1+=b1; v2+=b0; v3+=b1; }
                if(dogelu){ v0=gelu_f(v0); v1=gelu_f(v1); v2=gelu_f(v2); v3=gelu_f(v3); }
                long i0 = (long)r0*N + col, i1 = (long)r1*N + col;
                if(out16){
                    *(__half2*)(Ch + i0) = __floats2half2_rn(v0, v1);
                    *(__half2*)(Ch + i1) = __floats2half2_rn(v2, v3);
                } else {
                    if(res){
                        long j0 = (long)(r0 & rmask)*N + col;
                        long j1 = (long)(r1 & rmask)*N + col;
                        float2 rv0 = *(const float2*)(res + j0);
                        float2 rv1 = *(const float2*)(res + j1);
                        v0+=rv0.x; v1+=rv0.y; v2+=rv1.x; v3+=rv1.y;
                    }
                    *(float2*)(Cf + i0) = make_float2(v0, v1);
                    *(float2*)(Cf + i1) = make_float2(v2, v3);
                }
            }
        }
    }
}

// ---------------- fused flash attention: 3-stage cp.async K/V pipeline ----------------
#define QST 44
#define VST 36
#define K_ST (64*QST)
#define V_ST (72*VST)
#define FSMEM ((128*QST + 3*K_ST + 3*V_ST)*4)   // 87424 bytes

__global__ __launch_bounds__(256,2)
void flash_attn(const __half* __restrict__ q2, const __half* __restrict__ k2,
                const __half* __restrict__ v2t, __half* __restrict__ attn)
{
    extern __shared__ uint32_t fsm[];
    uint32_t* Qs = fsm;
    uint32_t* Ks = fsm + 128*QST;
    uint32_t* Vs = Ks + 3*K_ST;

    const int tid = threadIdx.x;
    const int lane = tid & 31, w = tid >> 5;
    const int g = lane >> 2, tq = lane & 3;
    const int qb = blockIdx.x, bh = blockIdx.y;

    const __half* Kg0 = k2  + (long)bh*IMG_TOK*HD;
    const __half* Vg0 = v2t + (long)bh*HD*IMG_TOK;

    auto loadKV = [&](int st, int kb){
        const __half* Kg = Kg0 + (long)kb*64*HD;
        for(int idx = tid; idx < 576; idx += 256){
            int r = idx/9, c = idx%9;
            cp16(Ks + st*K_ST + r*QST + c*4, Kg + (long)r*HD + c*8, 16);
        }
        const __half* Vg = Vg0 + kb*64;
        for(int idx = tid; idx < 576; idx += 256){
            int r = idx/8, c = idx%8;
            cp16(Vs + st*V_ST + r*VST + c*4, Vg + (long)r*IMG_TOK + c*8, 16);
        }
    };

    for(int idx = tid; idx < 3*64*4; idx += 256){
        int st = idx/256, rem = idx%256, r = rem>>2, c = rem&3;
        Ks[st*K_ST + r*QST + 36 + c] = 0;
    }
    const __half* Qg = q2 + ((long)bh*IMG_TOK + qb*128)*HD;
    for(int idx = tid; idx < 128*40; idx += 256){
        int r = idx/40, c = idx%40;
        Qs[r*QST + c] = (c < 36) ? *(const uint32_t*)(Qg + (long)r*HD + 2*c) : 0u;
    }

    loadKV(0, 0); CP_COMMIT();
    loadKV(1, 1); CP_COMMIT();
    __syncthreads();

    uint32_t qf[5][4];
    #pragma unroll
    for(int s=0;s<5;s++){
        qf[s][0] = Qs[(w*16+g  )*QST + s*8 + tq    ];
        qf[s][1] = Qs[(w*16+8+g)*QST + s*8 + tq    ];
        qf[s][2] = Qs[(w*16+g  )*QST + s*8 + tq + 4];
        qf[s][3] = Qs[(w*16+8+g)*QST + s*8 + tq + 4];
    }

    float m0 = -3.4e38f, m1 = -3.4e38f, l0 = 0.f, l1 = 0.f;
    float o[9][4];
    #pragma unroll
    for(int nt=0;nt<9;nt++){ o[nt][0]=0.f; o[nt][1]=0.f; o[nt][2]=0.f; o[nt][3]=0.f; }

    for(int kb=0; kb<16; kb++){
        if(kb+1 < 16){ CP_WAIT1(); } else { CP_WAIT0(); }
        __syncthreads();

        const uint32_t* Kst = Ks + (kb%3)*K_ST;
        const uint32_t* Vst = Vs + (kb%3)*V_ST;

        float sacc[8][4];
        #pragma unroll
        for(int nt=0;nt<8;nt++){ sacc[nt][0]=0.f; sacc[nt][1]=0.f; sacc[nt][2]=0.f; sacc[nt][3]=0.f; }
        #pragma unroll
        for(int s=0;s<5;s++){
            #pragma unroll
            for(int nt=0;nt<8;nt++){
                uint32_t bf[2];
                bf[0] = Kst[(nt*8+g)*QST + s*8 + tq    ];
                bf[1] = Kst[(nt*8+g)*QST + s*8 + tq + 4];
                mma16(sacc[nt], qf[s], bf);
            }
        }

        float rm0 = -3.4e38f, rm1 = -3.4e38f;
        #pragma unroll
        for(int nt=0;nt<8;nt++){
            rm0 = fmaxf(rm0, fmaxf(sacc[nt][0], sacc[nt][1]));
            rm1 = fmaxf(rm1, fmaxf(sacc[nt][2], sacc[nt][3]));
        }
        rm0 = fmaxf(rm0, __shfl_xor_sync(0xffffffffu, rm0, 1));
        rm0 = fmaxf(rm0, __shfl_xor_sync(0xffffffffu, rm0, 2));
        rm1 = fmaxf(rm1, __shfl_xor_sync(0xffffffffu, rm1, 1));
        rm1 = fmaxf(rm1, __shfl_xor_sync(0xffffffffu, rm1, 2));

        float m0n = fmaxf(m0, rm0), m1n = fmaxf(m1, rm1);
        float a0 = __expf(m0 - m0n), a1 = __expf(m1 - m1n);
        m0 = m0n; m1 = m1n;

        float rs0 = 0.f, rs1 = 0.f;
        #pragma unroll
        for(int nt=0;nt<8;nt++){
            sacc[nt][0] = __expf(sacc[nt][0] - m0n);
            sacc[nt][1] = __expf(sacc[nt][1] - m0n);
            sacc[nt][2] = __expf(sacc[nt][2] - m1n);
            sacc[nt][3] = __expf(sacc[nt][3] - m1n);
            rs0 += sacc[nt][0] + sacc[nt][1];
            rs1 += sacc[nt][2] + sacc[nt][3];
        }
        rs0 += __shfl_xor_sync(0xffffffffu, rs0, 1);
        rs0 += __shfl_xor_sync(0xffffffffu, rs0, 2);
        rs1 += __shfl_xor_sync(0xffffffffu, rs1, 1);
        rs1 += __shfl_xor_sync(0xffffffffu, rs1, 2);
        l0 = l0*a0 + rs0;
        l1 = l1*a1 + rs1;

        #pragma unroll
        for(int nt=0;nt<9;nt++){
            o[nt][0]*=a0; o[nt][1]*=a0; o[nt][2]*=a1; o[nt][3]*=a1;
        }

        #pragma unroll
        for(int ks=0;ks<4;ks++){
            uint32_t pf[4];
            pf[0] = h2u(sacc[2*ks  ][0], sacc[2*ks  ][1]);
            pf[1] = h2u(sacc[2*ks  ][2], sacc[2*ks  ][3]);
            pf[2] = h2u(sacc[2*ks+1][0], sacc[2*ks+1][1]);
            pf[3] = h2u(sacc[2*ks+1][2], sacc[2*ks+1][3]);
            #pragma unroll
            for(int nt=0;nt<9;nt++){
                uint32_t bf[2];
                bf[0] = Vst[(nt*8+g)*VST + ks*8 + tq    ];
                bf[1] = Vst[(nt*8+g)*VST + ks*8 + tq + 4];
                mma16(o[nt], pf, bf);
            }
        }

        if(kb+2 < 16){ loadKV((kb+2)%3, kb+2); CP_COMMIT(); }
    }

    float inv0 = 1.f/l0, inv1 = 1.f/l1;
    int b = bh >> 4, h = bh & 15;
    int t0 = qb*128 + w*16 + g;
    long base0 = (long)(b*IMG_TOK + t0    )*HIDDEN + h*HD;
    long base1 = (long)(b*IMG_TOK + t0 + 8)*HIDDEN + h*HD;
    #pragma unroll
    for(int nt=0;nt<9;nt++){
        int col = nt*8 + tq*2;
        *(__half2*)(attn + base0 + col) = __floats2half2_rn(o[nt][0]*inv0, o[nt][1]*inv0);
        *(__half2*)(attn + base1 + col) = __floats2half2_rn(o[nt][2]*inv1, o[nt][3]*inv1);
    }
}

// ---------------- LayerNorm (fp32 in, fp16 out; vectorized) ----------------
__global__ void ln_kernel(const float* __restrict__ x, const float* __restrict__ g,
                          const float* __restrict__ b, __half* __restrict__ y, int N)
{
    __shared__ float sh[32];
    const int n4 = N >> 2;
    const float4* X4 = (const float4*)(x + (long)blockIdx.x * N);
    const float4* G4 = (const float4*)g;
    const float4* B4 = (const float4*)b;
    __half2* Y2 = (__half2*)(y + (long)blockIdx.x * N);

    float s=0.f, ss=0.f;
    for(int c=threadIdx.x;c<n4;c+=blockDim.x){
        float4 v = X4[c];
        s  += v.x + v.y + v.z + v.w;
        ss += v.x*v.x + v.y*v.y + v.z*v.z + v.w*v.w;
    }
    s  = blockReduceSum(s,  sh);
    ss = blockReduceSum(ss, sh);
    float mu  = s  / (float)N;
    float var = ss / (float)N - mu*mu;
    float rs  = rsqrtf(var + 1e-6f);
    for(int c=threadIdx.x;c<n4;c+=blockDim.x){
        float4 v = X4[c];
        float4 gg = G4[c], bb = B4[c];
        Y2[2*c  ] = __floats2half2_rn((v.x-mu)*rs*gg.x + bb.x, (v.y-mu)*rs*gg.y + bb.y);
        Y2[2*c+1] = __floats2half2_rn((v.z-mu)*rs*gg.z + bb.z, (v.w-mu)*rs*gg.w + bb.w);
    }
}

// ---------------- RoPE tables ----------------
__global__ void init_rope()
{
    int gid = blockIdx.x*blockDim.x + threadIdx.x;
    if(gid >= IMG_TOK*HD) return;
    int d = gid % HD, tt = gid / HD;
    int iw=tt&1, ih=(tt>>1)&1, bw=(tt>>2)&15, bh=tt>>6;
    int gh = bh*2+ih, gw = bw*2+iw;
    int dd = d % 36;
    int pos, i;
    if(dd < 18){ i = dd;      pos = gh; }
    else       { i = dd - 18; pos = gw; }
    float inv = powf(10000.0f, -((float)(2*i)/36.0f));
    float ang = (float)pos * inv;
    g_cos[gid] = cosf(ang);
    g_sin[gid] = sinf(ang);
}

// ---------------- pos-embed precompute (bilinear) ----------------
__global__ void pe_precompute(const float* __restrict__ pe, float* __restrict__ dst)
{
    int gid = blockIdx.x*blockDim.x + threadIdx.x;
    if(gid >= IMG_TOK*HIDDEN) return;
    int j = gid % HIDDEN; int tt = gid / HIDDEN;
    int iw=tt&1, ih=(tt>>1)&1, bw=(tt>>2)&15, bh=tt>>6;
    int gh = bh*2+ih, gw = bw*2+iw;
    double hl = (double)gh*47.0/31.0;
    double wl = (double)gw*47.0/31.0;
    int h0=(int)hl; int h1=min(h0+1,47); float dh=(float)(hl-(double)h0);
    int w0=(int)wl; int w1=min(w0+1,47); float dw=(float)(wl-(double)w0);
    float p00 = pe[(h0*48+w0)*HIDDEN + j];
    float p01 = pe[(h0*48+w1)*HIDDEN + j];
    float p10 = pe[(h1*48+w0)*HIDDEN + j];
    float p11 = pe[(h1*48+w1)*HIDDEN + j];
    dst[gid] = (1.f-dh)*((1.f-dw)*p00 + dw*p01) + dh*((1.f-dw)*p10 + dw*p11);
}

// ---------------- fused RoPE(Q,K) + V transpose ----------------
__global__ void rope_pack2(const __half* __restrict__ qkv, __half* __restrict__ q2,
                           __half* __restrict__ k2, __half* __restrict__ v16t)
{
    __shared__ __half tile[64][80];
    const int tb = blockIdx.x, bh = blockIdx.y;
    const int b = bh >> 4, h = bh & 15;
    const int tid = threadIdx.x;

    for(int idx = tid; idx < 64*HD; idx += 256){
        int r = idx / HD, d = idx % HD;
        int tt = tb*64 + r;
        long base = (long)(b*IMG_TOK + tt)*(3*HIDDEN) + h*HD;
        float c  = g_cos[tt*HD + d];
        float sn = g_sin[tt*HD + d];
        float qd = __half2float(qkv[base + d]);
        float kd = __half2float(qkv[base + HIDDEN + d]);
        int   dp  = (d<36) ? d+36 : d-36;
        float sgn = (d<36) ? -1.f : 1.f;
        float qp = __half2float(qkv[base + dp]);
        float kp = __half2float(qkv[base + HIDDEN + dp]);
        long oi = ((long)bh*IMG_TOK + tt)*HD + d;
        q2[oi] = __float2half((qd*c + sgn*qp*sn) * SCALE_Q);
        k2[oi] = __float2half( kd*c + sgn*kp*sn);
        tile[r][d] = qkv[base + 2*HIDDEN + d];
    }
    __syncthreads();
    for(int idx = tid; idx < HD*64; idx += 256){
        int rr = idx / 64, cc = idx % 64;
        v16t[((long)bh*HD + rr)*IMG_TOK + tb*64 + cc] = tile[cc][rr];
    }
}

// ---------------- host helpers ----------------
static inline void gemma_s(cudaStream_t st, const __half*A,const __half*B,void*C,
                           const float*bias,const float*res,
                           int M,int N,int K,int flags){
    dim3 g((N+127)/128, M/128);
    gemm_a<<<g,256,GSMEM,st>>>(A,B,C,bias,res,M,N,K,flags);
}
static inline void gemma(const __half*A,const __half*B,void*C,const float*bias,const float*res,
                         int M,int N,int K,int flags){
    gemma_s(0, A,B,C,bias,res,M,N,K,flags);
}

extern "C" void kernel_launch(void* const* d_in, const int* in_sizes, int n_in,
                              void* d_out, int out_size)
{
    const float* pixel   = (const float*)d_in[0];
    const float* patch_w = (const float*)d_in[1];
    const float* patch_b = (const float*)d_in[2];
    const float* pos_e   = (const float*)d_in[3];
    const float* qkv_w   = (const float*)d_in[4];
    const float* qkv_b   = (const float*)d_in[5];
    const float* proj_w  = (const float*)d_in[6];
    const float* proj_b  = (const float*)d_in[7];
    const float* ln1_g   = (const float*)d_in[8];
    const float* ln1_b   = (const float*)d_in[9];
    const float* ln2_g   = (const float*)d_in[10];
    const float* ln2_b   = (const float*)d_in[11];
    const float* fc1_w   = (const float*)d_in[12];
    const float* fc1_b   = (const float*)d_in[13];
    const float* fc2_w   = (const float*)d_in[14];
    const float* fc2_b   = (const float*)d_in[15];
    const float* m_ln_g  = (const float*)d_in[16];
    const float* m_ln_b  = (const float*)d_in[17];
    const float* m_fc1_w = (const float*)d_in[18];
    const float* m_fc1_b = (const float*)d_in[19];
    const float* m_fc2_w = (const float*)d_in[20];
    const float* m_fc2_b = (const float*)d_in[21];
    const float* ds_ln_g = (const float*)d_in[22];
    const float* ds_ln_b = (const float*)d_in[23];
    const float* ds_fc1_w= (const float*)d_in[24];
    const float* ds_fc1_b= (const float*)d_in[25];
    const float* ds_fc2_w= (const float*)d_in[26];
    const float* ds_fc2_b= (const float*)d_in[27];
    float* out = (float*)d_out;

    cudaFuncSetAttribute(gemm_a, cudaFuncAttributeMaxDynamicSharedMemorySize, GSMEM);
    cudaFuncSetAttribute(flash_attn, cudaFuncAttributeMaxDynamicSharedMemorySize, FSMEM);

    static cudaStream_t s_side = [](){ cudaStream_t t; cudaStreamCreate(&t); return t; }();
    auto mkev = [](){ cudaEvent_t e; cudaEventCreateWithFlags(&e, cudaEventDisableTiming); return e; };
    static cudaEvent_t s_e0    = mkev();
    static cudaEvent_t s_epe   = mkev();
    static cudaEvent_t s_eqkv  = mkev();
    static cudaEvent_t s_emlp  = mkev();
    static cudaEvent_t s_emrg  = mkev();
    static cudaEvent_t s_fork0 = mkev();
    static cudaEvent_t s_fork1 = mkev();
    static cudaEvent_t s_lnd0  = mkev();
    static cudaEvent_t s_lnd1  = mkev();
    static cudaEvent_t s_join  = mkev();

    float *px, *ppe;
    __half *pw16,*pqw16,*ppw16,*pf1w16,*pf2w16,*pm1w16,*pm2w16,*pd1w16,*pd2w16,*ppx16;
    __half *pxn16,*pqkv16,*pq16,*pk16,*pv16t,*pat16,*ph16,*pmh16,*pmf16,*pdh16,*pdf16;
    cudaGetSymbolAddress((void**)&px,    g_x);
    cudaGetSymbolAddress((void**)&ppe,   g_pe);
    cudaGetSymbolAddress((void**)&pw16,  w16_patch);
    cudaGetSymbolAddress((void**)&pqw16, w16_qkv);
    cudaGetSymbolAddress((void**)&ppw16, w16_proj);
    cudaGetSymbolAddress((void**)&pf1w16,w16_fc1);
    cudaGetSymbolAddress((void**)&pf2w16,w16_fc2);
    cudaGetSymbolAddress((void**)&pm1w16,w16_mfc1);
    cudaGetSymbolAddress((void**)&pm2w16,w16_mfc2);
    cudaGetSymbolAddress((void**)&pd1w16,w16_dfc1);
    cudaGetSymbolAddress((void**)&pd2w16,w16_dfc2);
    cudaGetSymbolAddress((void**)&ppx16, g_px16);
    cudaGetSymbolAddress((void**)&pxn16, g_xn16);
    cudaGetSymbolAddress((void**)&pqkv16,g_qkv16);
    cudaGetSymbolAddress((void**)&pq16,  g_q16);
    cudaGetSymbolAddress((void**)&pk16,  g_k16);
    cudaGetSymbolAddress((void**)&pv16t, g_v16t);
    cudaGetSymbolAddress((void**)&pat16, g_at16);
    cudaGetSymbolAddress((void**)&ph16,  g_h16);
    cudaGetSymbolAddress((void**)&pmh16, g_mh16);
    cudaGetSymbolAddress((void**)&pmf16, g_mf16);
    cudaGetSymbolAddress((void**)&pdh16, g_dh16);
    cudaGetSymbolAddress((void**)&pdf16, g_df16);

    const int EW = 256;

    auto F2Hs = [&](cudaStream_t st, const float* s, __half* d, long n){
        long n4 = n/4;
        int grid = (int)((n4 + 255)/256); if(grid > 4096) grid = 4096;
        f2h<<<grid, 256, 0, st>>>((const float4*)s, (__half2*)d, n4);
    };

    // fork side stream at entry
    cudaEventRecord(s_e0, 0);
    cudaStreamWaitEvent(s_side, s_e0, 0);

    // main: immediately-needed work
    init_rope<<<(IMG_TOK*HD + EW-1)/EW, EW>>>();
    F2Hs(0, pixel,   ppx16, (long)SEQ*PATCHD);
    F2Hs(0, patch_w, pw16,  (long)HIDDEN*PATCHD);

    // side: pos-embed precompute, then staged weight conversions
    pe_precompute<<<(IMG_TOK*HIDDEN + EW-1)/EW, EW, 0, s_side>>>(pos_e, ppe);
    cudaEventRecord(s_epe, s_side);
    F2Hs(s_side, qkv_w, pqw16, (long)DEPTH*3*HIDDEN*HIDDEN);
    cudaEventRecord(s_eqkv, s_side);
    F2Hs(s_side, proj_w, ppw16,  (long)DEPTH*HIDDEN*HIDDEN);
    F2Hs(s_side, fc1_w,  pf1w16, (long)DEPTH*INTER*HIDDEN);
    F2Hs(s_side, fc2_w,  pf2w16, (long)DEPTH*HIDDEN*INTER);
    cudaEventRecord(s_emlp, s_side);
    F2Hs(s_side, ds_fc1_w, pd1w16, (long)2*MERGED*MERGED);
    F2Hs(s_side, ds_fc2_w, pd2w16, (long)2*OUTH*MERGED);
    F2Hs(s_side, m_fc1_w,  pm1w16, (long)MERGED*MERGED);
    F2Hs(s_side, m_fc2_w,  pm2w16, (long)OUTH*MERGED);
    cudaEventRecord(s_emrg, s_side);

    // patch embed with fused pos-embed residual (row wraps at 1024)
    cudaStreamWaitEvent(0, s_epe, 0);
    gemma(ppx16, pw16, px, patch_b, ppe, SEQ, HIDDEN, PATCHD, 4);

    for(int i=0;i<DEPTH;i++){
        ln_kernel<<<SEQ,256>>>(px, ln1_g+(long)i*HIDDEN, ln1_b+(long)i*HIDDEN, pxn16, HIDDEN);
        if(i==0) cudaStreamWaitEvent(0, s_eqkv, 0);
        gemma(pxn16, pqw16+(long)i*3*HIDDEN*HIDDEN, pqkv16, qkv_b+(long)i*3*HIDDEN, nullptr,
              SEQ, 3*HIDDEN, HIDDEN, 2);
        rope_pack2<<<dim3(16, NBH), 256>>>(pqkv16, pq16, pk16, pv16t);
        flash_attn<<<dim3(8, NBH), 256, FSMEM>>>(pq16, pk16, pv16t, pat16);
        if(i==0) cudaStreamWaitEvent(0, s_emlp, 0);
        if(i==3) cudaStreamWaitEvent(0, s_lnd0, 0);   // ds0 LN finished reading px
        if(i==5) cudaStreamWaitEvent(0, s_lnd1, 0);   // ds1 LN finished reading px
        gemma(pat16, ppw16+(long)i*HIDDEN*HIDDEN, px, proj_b+(long)i*HIDDEN, px,
              SEQ, HIDDEN, HIDDEN, 0);

        ln_kernel<<<SEQ,256>>>(px, ln2_g+(long)i*HIDDEN, ln2_b+(long)i*HIDDEN, pxn16, HIDDEN);
        gemma(pxn16, pf1w16+(long)i*INTER*HIDDEN, ph16, fc1_b+(long)i*INTER, nullptr,
              SEQ, INTER, HIDDEN, 1|2);
        gemma(ph16, pf2w16+(long)i*HIDDEN*INTER, px, fc2_b+(long)i*HIDDEN, px,
              SEQ, HIDDEN, INTER, 0);

        if(i==2 || i==4){
            int j = (i==2) ? 0 : 1;
            __half* dh = pdh16 + (long)j*1024*MERGED;
            __half* df = pdf16 + (long)j*1024*MERGED;
            // fork after fc2: px is final for layer i; side runs LN + both GEMMs
            cudaEvent_t fk = (j==0) ? s_fork0 : s_fork1;
            cudaEventRecord(fk, 0);
            cudaStreamWaitEvent(s_side, fk, 0);
            ln_kernel<<<1024,256,0,s_side>>>(px, ds_ln_g+(long)j*MERGED, ds_ln_b+(long)j*MERGED, dh, MERGED);
            cudaEventRecord((j==0) ? s_lnd0 : s_lnd1, s_side);
            gemma_s(s_side, dh, pd1w16+(long)j*MERGED*MERGED, df, ds_fc1_b+(long)j*MERGED, nullptr,
                    1024, MERGED, MERGED, 1|2);
            gemma_s(s_side, df, pd2w16+(long)j*OUTH*MERGED, out+(long)(1+j)*1024*OUTH,
                    ds_fc2_b+(long)j*OUTH, nullptr,
                    1024, OUTH, MERGED, 0);
            if(j==1) cudaEventRecord(s_join, s_side);
        }
    }

    ln_kernel<<<SEQ,256>>>(px, m_ln_g, m_ln_b, pmh16, HIDDEN);
    cudaStreamWaitEvent(0, s_emrg, 0);
    gemma(pmh16, pm1w16, pmf16, m_fc1_b, nullptr, 1024, MERGED, MERGED, 1|2);
    gemma(pmf16, pm2w16, out, m_fc2_b, nullptr, 1024, OUTH, MERGED, 0);

    cudaStreamWaitEvent(0, s_join, 0);
}